// round 4
// baseline (speedup 1.0000x reference)
#include <cuda_runtime.h>

typedef unsigned long long u64;

#define B_MAX 256

// Scratch (static device globals — no allocation in kernel_launch)
__device__ float g_emb[B_MAX * 3 * 32 * 32 * 32];  // [b][c][i][t][j]
__device__ float g_sig[B_MAX * 3 * 32 * 32 * 32];  // sigmoid(LN(.)) gate [b][c][i][t][j]
__device__ float g_sg2[B_MAX * 3 * 32 * 32];       // sigmoid(LN(x-branch)) [b][c][tok][feat]

// ---------------- packed f32x2 helpers ----------------
__device__ __forceinline__ u64 pack2(float lo, float hi) {
    u64 r; asm("mov.b64 %0, {%1, %2};" : "=l"(r) : "f"(lo), "f"(hi)); return r;
}
__device__ __forceinline__ void unpack2(u64 v, float& lo, float& hi) {
    asm("mov.b64 {%0, %1}, %2;" : "=f"(lo), "=f"(hi) : "l"(v));
}
__device__ __forceinline__ u64 fma2(u64 a, u64 b, u64 c) {
    u64 d; asm("fma.rn.f32x2 %0, %1, %2, %3;" : "=l"(d) : "l"(a), "l"(b), "l"(c)); return d;
}
__device__ __forceinline__ u64 mul2(u64 a, u64 b) {
    u64 d; asm("mul.rn.f32x2 %0, %1, %2;" : "=l"(d) : "l"(a), "l"(b)); return d;
}
__device__ __forceinline__ float sigmoid_(float v) { return 1.0f / (1.0f + __expf(-v)); }

// ---------------------------------------------------------------------------
// K1: emb[b,c,i,t,j] = sum_d x[b,c,t,d,i] * pos_y[c,j,d]
// ---------------------------------------------------------------------------
__global__ void __launch_bounds__(256) k_emb(const float* __restrict__ x,
                                             const float* __restrict__ pos)
{
    __shared__ float xs[32 * 33]; // xs[d][i]
    __shared__ float ps[32 * 36]; // ps[j][d]

    int bct = blockIdx.x;
    int t   = bct & 31;
    int bc  = bct >> 5;
    int c   = bc % 3;
    int tid = threadIdx.x;

    float4 xv = ((const float4*)(x + (size_t)bct * 1024))[tid];
    int rd = tid >> 3, c0 = (tid & 7) * 4;
    xs[rd * 33 + c0 + 0] = xv.x; xs[rd * 33 + c0 + 1] = xv.y;
    xs[rd * 33 + c0 + 2] = xv.z; xs[rd * 33 + c0 + 3] = xv.w;

    float4 pv = ((const float4*)(pos + c * 1024))[tid];
    ps[rd * 36 + c0 + 0] = pv.x; ps[rd * 36 + c0 + 1] = pv.y;
    ps[rd * 36 + c0 + 2] = pv.z; ps[rd * 36 + c0 + 3] = pv.w;
    __syncthreads();

    int i = tid >> 3, j0 = (tid & 7) * 4;
    float xc[32];
#pragma unroll
    for (int d = 0; d < 32; d++) xc[d] = xs[d * 33 + i];

    float a0 = 0.f, a1 = 0.f, a2 = 0.f, a3 = 0.f;
#pragma unroll
    for (int d4 = 0; d4 < 8; d4++) {
        float4 p;
        p = *(const float4*)(ps + (j0 + 0) * 36 + 4 * d4);
        a0 = fmaf(xc[4*d4], p.x, a0); a0 = fmaf(xc[4*d4+1], p.y, a0);
        a0 = fmaf(xc[4*d4+2], p.z, a0); a0 = fmaf(xc[4*d4+3], p.w, a0);
        p = *(const float4*)(ps + (j0 + 1) * 36 + 4 * d4);
        a1 = fmaf(xc[4*d4], p.x, a1); a1 = fmaf(xc[4*d4+1], p.y, a1);
        a1 = fmaf(xc[4*d4+2], p.z, a1); a1 = fmaf(xc[4*d4+3], p.w, a1);
        p = *(const float4*)(ps + (j0 + 2) * 36 + 4 * d4);
        a2 = fmaf(xc[4*d4], p.x, a2); a2 = fmaf(xc[4*d4+1], p.y, a2);
        a2 = fmaf(xc[4*d4+2], p.z, a2); a2 = fmaf(xc[4*d4+3], p.w, a2);
        p = *(const float4*)(ps + (j0 + 3) * 36 + 4 * d4);
        a3 = fmaf(xc[4*d4], p.x, a3); a3 = fmaf(xc[4*d4+1], p.y, a3);
        a3 = fmaf(xc[4*d4+2], p.z, a3); a3 = fmaf(xc[4*d4+3], p.w, a3);
    }
    float4 ov = make_float4(a0, a1, a2, a3);
    *(float4*)(g_emb + ((size_t)bc * 32 + i) * 1024 + t * 32 + j0) = ov;
}

// ---------------------------------------------------------------------------
// Warp attention, weights read DIRECTLY from global (L1-resident broadcast,
// off the smem crossbar). Only K/V token data goes through smem.
// Full fusion: residual + LN + sigmoid, writes gate.
// ---------------------------------------------------------------------------
__device__ __forceinline__ void warp_attn_g(
    int lane,
    const float* __restrict__ eg,   // E tile [t][j], 32x32 (global)
    float* __restrict__ og,         // gate output [t][j] (global)
    const float* __restrict__ W,    // Wqvk [96][32] (global, L1-hot)
    const float* __restrict__ W0,   // W0 [32][32] (global, L1-hot)
    const float* __restrict__ gam,  // gamma[32] (global)
    const float* __restrict__ bet,  // beta[32]  (global)
    float* __restrict__ skv)        // 384 floats smem, warp-private
{
    u64 e2[16];
    {
        const ulonglong2* ep = (const ulonglong2*)(eg + lane * 32);
#pragma unroll
        for (int j = 0; j < 8; j++) { ulonglong2 v = ep[j]; e2[2*j] = v.x; e2[2*j+1] = v.y; }
    }
    float rr[32];
#pragma unroll
    for (int j = 0; j < 16; j++) unpack2(e2[j], rr[2*j], rr[2*j+1]);

#pragma unroll 1
    for (int h = 0; h < 8; h++) {
        // ---- q,k,v for head h; weights via broadcast LDG (L1) ----
        float q[4], kk[4], vv[4];
#pragma unroll
        for (int d = 0; d < 4; d++) {
            const ulonglong2* wq = (const ulonglong2*)(W + (d * 24 + h)      * 32);
            const ulonglong2* wk = (const ulonglong2*)(W + (d * 24 + 8 + h)  * 32);
            const ulonglong2* wv = (const ulonglong2*)(W + (d * 24 + 16 + h) * 32);
            u64 aq = 0, ak = 0, av = 0;
#pragma unroll
            for (int j = 0; j < 8; j++) {
                ulonglong2 w;
                w = wq[j]; aq = fma2(e2[2*j+1], w.y, fma2(e2[2*j], w.x, aq));
                w = wk[j]; ak = fma2(e2[2*j+1], w.y, fma2(e2[2*j], w.x, ak));
                w = wv[j]; av = fma2(e2[2*j+1], w.y, fma2(e2[2*j], w.x, av));
            }
            float a, b;
            unpack2(aq, a, b); q[d]  = (a + b) * 0.5f;   // fold DH^-0.5
            unpack2(ak, a, b); kk[d] = a + b;
            unpack2(av, a, b); vv[d] = a + b;
        }
        *(float4*)(skv + lane * 12)     = make_float4(kk[0], kk[1], kk[2], kk[3]);
        *(float4*)(skv + lane * 12 + 4) = make_float4(vv[0], vv[1], vv[2], vv[3]);
        u64 q01 = pack2(q[0], q[1]), q23 = pack2(q[2], q[3]);
        __syncwarp();

        // ---- fused softmax + AV (scores tiny; no max-subtract needed) ----
        float sum = 0.f;
        u64 a01 = 0, a23 = 0;
#pragma unroll
        for (int s = 0; s < 32; s++) {
            ulonglong2 k2 = *(const ulonglong2*)(skv + s * 12);
            ulonglong2 v2 = *(const ulonglong2*)(skv + s * 12 + 4);
            u64 t = fma2(q23, k2.y, mul2(q01, k2.x));
            float ta, tb; unpack2(t, ta, tb);
            float p = __expf(ta + tb);
            sum += p;
            u64 p2 = pack2(p, p);
            a01 = fma2(p2, v2.x, a01);
            a23 = fma2(p2, v2.y, a23);
        }
        float inv = 1.f / sum;
        float oa, ob, oc, od;
        unpack2(a01, oa, ob); unpack2(a23, oc, od);
        u64 o01 = pack2(oa * inv, ob * inv), o23 = pack2(oc * inv, od * inv);

        // ---- incremental W0 (global broadcast reads): rr[j] += o_h . W0[j][4h..] ----
        const float* w0h = W0 + 4 * h;
#pragma unroll
        for (int j = 0; j < 32; j += 2) {
            ulonglong2 wa = *(const ulonglong2*)(w0h + j * 32);
            ulonglong2 wb = *(const ulonglong2*)(w0h + (j + 1) * 32);
            u64 ra = fma2(o23, wa.y, mul2(o01, wa.x));
            u64 rb = fma2(o23, wb.y, mul2(o01, wb.x));
            float xa, xb;
            unpack2(ra, xa, xb); rr[j]     += xa + xb;
            unpack2(rb, xa, xb); rr[j + 1] += xa + xb;
        }
        __syncwarp();  // all lanes done with skv before next head overwrites
    }

    // ---- layernorm + sigmoid + direct store ----
    float s1 = 0.f;
#pragma unroll
    for (int j = 0; j < 32; j++) s1 += rr[j];
    float mu = s1 * 0.03125f;
    float sq = 0.f;
#pragma unroll
    for (int j = 0; j < 32; j++) { float d = rr[j] - mu; sq = fmaf(d, d, sq); }
    float rstd = rsqrtf(sq * 0.03125f + 1e-5f);

    float* po = og + lane * 32;
#pragma unroll
    for (int j = 0; j < 32; j += 4) {
        float4 gm = *(const float4*)(gam + j);
        float4 bt = *(const float4*)(bet + j);
        float4 v;
        v.x = sigmoid_((rr[j]     - mu) * rstd * gm.x + bt.x);
        v.y = sigmoid_((rr[j + 1] - mu) * rstd * gm.y + bt.y);
        v.z = sigmoid_((rr[j + 2] - mu) * rstd * gm.z + bt.z);
        v.w = sigmoid_((rr[j + 3] - mu) * rstd * gm.w + bt.w);
        *(float4*)(po + j) = v;
    }
}

// ---------------------------------------------------------------------------
// K2: x-branch. 1 warp per (b,c) on emb_last = emb[b,2,31]. Writes g_sg2.
// ---------------------------------------------------------------------------
#define WX 4
__global__ void __launch_bounds__(WX * 32) k_attn_x(
    const float* __restrict__ Wqvk, const float* __restrict__ W0,
    const float* __restrict__ g, const float* __restrict__ b)
{
    __shared__ float skv[WX * 384];
    int tid = threadIdx.x;
    int w = tid >> 5, lane = tid & 31;
    int lin = blockIdx.x * WX + w;   // b*3 + c
    int bb = lin / 3, c = lin % 3;
    const float* eg = g_emb + (((size_t)bb * 3 + 2) * 32 + 31) * 1024;
    float* og = g_sg2 + (size_t)lin * 1024;
    warp_attn_g(lane, eg, og, Wqvk + c * 3072, W0 + c * 1024, g, b, skv + w * 384);
}

// ---------------------------------------------------------------------------
// K3: y-branch. 1 warp per (b,c,i). Writes gate to g_sig.
// ---------------------------------------------------------------------------
#define WY 4
__global__ void __launch_bounds__(WY * 32, 4) k_attn_y(
    const float* __restrict__ Wqvk, const float* __restrict__ W0,
    const float* __restrict__ g, const float* __restrict__ b)
{
    __shared__ float skv[WY * 384];
    int tid = threadIdx.x;
    int w = tid >> 5, lane = tid & 31;
    int bc = blockIdx.x >> 3;
    int iblk = blockIdx.x & 7;
    int c = bc % 3;

    int i = iblk * WY + w;
    const float* eg = g_emb + ((size_t)bc * 32 + i) * 1024;
    float* og       = g_sig + ((size_t)bc * 32 + i) * 1024;
    warp_attn_g(lane, eg, og, Wqvk + c * 3072, W0 + c * 1024, g, b, skv + w * 384);
}

// ---------------------------------------------------------------------------
// K4: out[b,c,t,j,i] = sg2[b,c,i,t] * g_sig[b,c,i,t,j] * x[b,c,t,j,i]
// ---------------------------------------------------------------------------
__global__ void __launch_bounds__(256) k_final(const float* __restrict__ x,
                                               float* __restrict__ out)
{
    __shared__ float gs[32 * 33]; // gs[i][j]
    __shared__ float ss[32];
    int bct = blockIdx.x;
    int t = bct & 31;
    int bc = bct >> 5;
    int tid = threadIdx.x;

    int i = tid >> 3, j0 = (tid & 7) * 4;
    float4 gv = *(const float4*)(g_sig + ((size_t)bc * 32 + i) * 1024 + t * 32 + j0);
    gs[i * 33 + j0 + 0] = gv.x; gs[i * 33 + j0 + 1] = gv.y;
    gs[i * 33 + j0 + 2] = gv.z; gs[i * 33 + j0 + 3] = gv.w;
    if (tid < 32) ss[tid] = g_sg2[(size_t)bc * 1024 + tid * 32 + t];
    __syncthreads();

    float4 xv = ((const float4*)(x + (size_t)bct * 1024))[tid];
    int jj = tid >> 3, i0 = (tid & 7) * 4;
    float4 ov;
    ov.x = ss[i0 + 0] * gs[(i0 + 0) * 33 + jj] * xv.x;
    ov.y = ss[i0 + 1] * gs[(i0 + 1) * 33 + jj] * xv.y;
    ov.z = ss[i0 + 2] * gs[(i0 + 2) * 33 + jj] * xv.z;
    ov.w = ss[i0 + 3] * gs[(i0 + 3) * 33 + jj] * xv.w;
    ((float4*)(out + (size_t)bct * 1024))[tid] = ov;
}

// ---------------------------------------------------------------------------
extern "C" void kernel_launch(void* const* d_in, const int* in_sizes, int n_in,
                              void* d_out, int out_size)
{
    const float* x   = (const float*)d_in[0];
    const float* pos = (const float*)d_in[1];
    const float* Wqy = (const float*)d_in[2];
    const float* W0y = (const float*)d_in[3];
    const float* gy  = (const float*)d_in[4];
    const float* by  = (const float*)d_in[5];
    const float* Wqx = (const float*)d_in[6];
    const float* W0x = (const float*)d_in[7];
    const float* gx  = (const float*)d_in[8];
    const float* bx  = (const float*)d_in[9];
    float* out = (float*)d_out;

    int B = in_sizes[0] / 98304;  // 3*32*32*32

    k_emb<<<B * 96, 256>>>(x, pos);
    k_attn_x<<<(B * 3) / WX, WX * 32>>>(Wqx, W0x, gx, bx);
    k_attn_y<<<B * 24, WY * 32>>>(Wqy, W0y, gy, by);
    k_final<<<B * 96, 256>>>(x, out);
}

// round 5
// speedup vs baseline: 1.1083x; 1.1083x over previous
#include <cuda_runtime.h>
#include <cuda_fp16.h>

typedef unsigned long long u64;

#define B_MAX 256

__device__ float g_emb[B_MAX * 3 * 32 * 32 * 32];  // [b][c][i][t][j]
__device__ float g_sig[B_MAX * 3 * 32 * 32 * 32];  // y-branch RAW W0 projection
__device__ float g_sg2[B_MAX * 3 * 32 * 32];       // sigmoid(LN(x-branch))

// ---------------- packed f32x2 helpers ----------------
__device__ __forceinline__ u64 pack2(float lo, float hi) {
    u64 r; asm("mov.b64 %0, {%1, %2};" : "=l"(r) : "f"(lo), "f"(hi)); return r;
}
__device__ __forceinline__ void unpack2(u64 v, float& lo, float& hi) {
    asm("mov.b64 {%0, %1}, %2;" : "=f"(lo), "=f"(hi) : "l"(v));
}
__device__ __forceinline__ u64 fma2(u64 a, u64 b, u64 c) {
    u64 d; asm("fma.rn.f32x2 %0, %1, %2, %3;" : "=l"(d) : "l"(a), "l"(b), "l"(c)); return d;
}
__device__ __forceinline__ u64 mul2(u64 a, u64 b) {
    u64 d; asm("mul.rn.f32x2 %0, %1, %2;" : "=l"(d) : "l"(a), "l"(b)); return d;
}
__device__ __forceinline__ u64 f2u(float2 v) {
    u64 r; asm("mov.b64 %0, {%1, %2};" : "=l"(r) : "f"(v.x), "f"(v.y)); return r;
}
__device__ __forceinline__ unsigned h2u(__half2 h) { return *(unsigned*)&h; }
__device__ __forceinline__ float2 u2f2(unsigned u) { __half2 h = *(__half2*)&u; return __half22float2(h); }
__device__ __forceinline__ float sigmoid_(float v) { return 1.0f / (1.0f + __expf(-v)); }

// ---------------------------------------------------------------------------
// K1: emb[b,c,i,t,j] = sum_d x[b,c,t,d,i] * pos_y[c,j,d]
// ---------------------------------------------------------------------------
__global__ void __launch_bounds__(256) k_emb(const float* __restrict__ x,
                                             const float* __restrict__ pos)
{
    __shared__ float xs[32 * 33]; // xs[d][i]
    __shared__ float ps[32 * 36]; // ps[j][d]

    int bct = blockIdx.x;
    int t   = bct & 31;
    int bc  = bct >> 5;
    int c   = bc % 3;
    int tid = threadIdx.x;

    float4 xv = ((const float4*)(x + (size_t)bct * 1024))[tid];
    int rd = tid >> 3, c0 = (tid & 7) * 4;
    xs[rd * 33 + c0 + 0] = xv.x; xs[rd * 33 + c0 + 1] = xv.y;
    xs[rd * 33 + c0 + 2] = xv.z; xs[rd * 33 + c0 + 3] = xv.w;

    float4 pv = ((const float4*)(pos + c * 1024))[tid];
    ps[rd * 36 + c0 + 0] = pv.x; ps[rd * 36 + c0 + 1] = pv.y;
    ps[rd * 36 + c0 + 2] = pv.z; ps[rd * 36 + c0 + 3] = pv.w;
    __syncthreads();

    int i = tid >> 3, j0 = (tid & 7) * 4;
    float xc[32];
#pragma unroll
    for (int d = 0; d < 32; d++) xc[d] = xs[d * 33 + i];

    float a0 = 0.f, a1 = 0.f, a2 = 0.f, a3 = 0.f;
#pragma unroll
    for (int d4 = 0; d4 < 8; d4++) {
        float4 p;
        p = *(const float4*)(ps + (j0 + 0) * 36 + 4 * d4);
        a0 = fmaf(xc[4*d4], p.x, a0); a0 = fmaf(xc[4*d4+1], p.y, a0);
        a0 = fmaf(xc[4*d4+2], p.z, a0); a0 = fmaf(xc[4*d4+3], p.w, a0);
        p = *(const float4*)(ps + (j0 + 1) * 36 + 4 * d4);
        a1 = fmaf(xc[4*d4], p.x, a1); a1 = fmaf(xc[4*d4+1], p.y, a1);
        a1 = fmaf(xc[4*d4+2], p.z, a1); a1 = fmaf(xc[4*d4+3], p.w, a1);
        p = *(const float4*)(ps + (j0 + 2) * 36 + 4 * d4);
        a2 = fmaf(xc[4*d4], p.x, a2); a2 = fmaf(xc[4*d4+1], p.y, a2);
        a2 = fmaf(xc[4*d4+2], p.z, a2); a2 = fmaf(xc[4*d4+3], p.w, a2);
        p = *(const float4*)(ps + (j0 + 3) * 36 + 4 * d4);
        a3 = fmaf(xc[4*d4], p.x, a3); a3 = fmaf(xc[4*d4+1], p.y, a3);
        a3 = fmaf(xc[4*d4+2], p.z, a3); a3 = fmaf(xc[4*d4+3], p.w, a3);
    }
    float4 ov = make_float4(a0, a1, a2, a3);
    *(float4*)(g_emb + ((size_t)bc * 32 + i) * 1024 + t * 32 + j0) = ov;
}

// ---------------------------------------------------------------------------
// K3: y-branch, TWO tiles per warp. Weight LDS amortized 2x, K/V in fp16.
// Emits RAW W0 projection; LN/sigmoid deferred to k_final.
// smem per CTA: sW 3072 | sW0 1024 | skv 4w x 256 | so 4w x 2048  (53 KB dyn)
// ---------------------------------------------------------------------------
#define WY 4
__global__ void __launch_bounds__(WY * 32, 4) k_attn_y2(
    const float* __restrict__ Wqvk, const float* __restrict__ W0, int base)
{
    extern __shared__ float sm[];
    float* sW  = sm;
    float* sW0 = sm + 3072;

    int tid = threadIdx.x;
    int w = tid >> 5, lane = tid & 31;
    float* skv = sm + 4096 + w * 256;   // 32 rows x 8 floats: [uint4 A][uint4 B]
    float* so  = sm + 5120 + w * 2048;  // o stash: tileA [0..1024), tileB [1024..2048)

    int cid = base + blockIdx.x;
    int bc = cid >> 2;       // b*3 + c
    int ib = cid & 3;
    int c = bc % 3;

    for (int k = tid; k < 768; k += WY * 32) ((float4*)sW)[k]  = ((const float4*)(Wqvk + c * 3072))[k];
    for (int k = tid; k < 256; k += WY * 32) ((float4*)sW0)[k] = ((const float4*)(W0 + c * 1024))[k];
    __syncthreads();

    int i0 = ib * 8 + w * 2;
    const float* egA = g_emb + ((size_t)bc * 32 + i0) * 1024;
    const float* egB = egA + 1024;
    float* ogA = g_sig + ((size_t)bc * 32 + i0) * 1024;
    float* ogB = ogA + 1024;

    // own token rows for both tiles -> packed regs (64 regs)
    u64 e2A[16], e2B[16];
    {
        const ulonglong2* ea = (const ulonglong2*)(egA + lane * 32);
        const ulonglong2* eb = (const ulonglong2*)(egB + lane * 32);
#pragma unroll
        for (int j = 0; j < 8; j++) {
            ulonglong2 va = ea[j]; e2A[2*j] = va.x; e2A[2*j+1] = va.y;
            ulonglong2 vb = eb[j]; e2B[2*j] = vb.x; e2B[2*j+1] = vb.y;
        }
    }

#pragma unroll 1
    for (int h = 0; h < 8; h++) {
        float qA[4], kA[4], vA[4], qB[4], kB[4], vB[4];
#pragma unroll
        for (int d = 0; d < 4; d++) {
            const ulonglong2* wq = (const ulonglong2*)(sW + (d * 24 + h)      * 32);
            const ulonglong2* wk = (const ulonglong2*)(sW + (d * 24 + 8 + h)  * 32);
            const ulonglong2* wv = (const ulonglong2*)(sW + (d * 24 + 16 + h) * 32);
            u64 aqA = 0, akA = 0, avA = 0, aqB = 0, akB = 0, avB = 0;
#pragma unroll
            for (int j = 0; j < 8; j++) {
                ulonglong2 ww;
                ww = wq[j];
                aqA = fma2(e2A[2*j+1], ww.y, fma2(e2A[2*j], ww.x, aqA));
                aqB = fma2(e2B[2*j+1], ww.y, fma2(e2B[2*j], ww.x, aqB));
                ww = wk[j];
                akA = fma2(e2A[2*j+1], ww.y, fma2(e2A[2*j], ww.x, akA));
                akB = fma2(e2B[2*j+1], ww.y, fma2(e2B[2*j], ww.x, akB));
                ww = wv[j];
                avA = fma2(e2A[2*j+1], ww.y, fma2(e2A[2*j], ww.x, avA));
                avB = fma2(e2B[2*j+1], ww.y, fma2(e2B[2*j], ww.x, avB));
            }
            float a, b;
            unpack2(aqA, a, b); qA[d] = (a + b) * 0.5f;   // fold DH^-0.5
            unpack2(akA, a, b); kA[d] = a + b;
            unpack2(avA, a, b); vA[d] = a + b;
            unpack2(aqB, a, b); qB[d] = (a + b) * 0.5f;
            unpack2(akB, a, b); kB[d] = a + b;
            unpack2(avB, a, b); vB[d] = a + b;
        }
        // fp16 K/V to smem: one uint4 per tile
        {
            uint4 uA, uB;
            uA.x = h2u(__floats2half2_rn(kA[0], kA[1]));
            uA.y = h2u(__floats2half2_rn(kA[2], kA[3]));
            uA.z = h2u(__floats2half2_rn(vA[0], vA[1]));
            uA.w = h2u(__floats2half2_rn(vA[2], vA[3]));
            uB.x = h2u(__floats2half2_rn(kB[0], kB[1]));
            uB.y = h2u(__floats2half2_rn(kB[2], kB[3]));
            uB.z = h2u(__floats2half2_rn(vB[0], vB[1]));
            uB.w = h2u(__floats2half2_rn(vB[2], vB[3]));
            *(uint4*)(skv + lane * 8)     = uA;
            *(uint4*)(skv + lane * 8 + 4) = uB;
        }
        u64 q01A = pack2(qA[0], qA[1]), q23A = pack2(qA[2], qA[3]);
        u64 q01B = pack2(qB[0], qB[1]), q23B = pack2(qB[2], qB[3]);
        __syncwarp();

        float sumA = 0.f, sumB = 0.f;
        u64 aA01 = 0, aA23 = 0, aB01 = 0, aB23 = 0;
#pragma unroll 8
        for (int s = 0; s < 32; s++) {
            uint4 uA = *(uint4*)(skv + s * 8);
            uint4 uB = *(uint4*)(skv + s * 8 + 4);
            // tile A
            u64 tA = fma2(q23A, f2u(u2f2(uA.y)), mul2(q01A, f2u(u2f2(uA.x))));
            float ta, tb; unpack2(tA, ta, tb);
            float pA = __expf(ta + tb);
            sumA += pA;
            u64 p2A = pack2(pA, pA);
            aA01 = fma2(p2A, f2u(u2f2(uA.z)), aA01);
            aA23 = fma2(p2A, f2u(u2f2(uA.w)), aA23);
            // tile B
            u64 tB = fma2(q23B, f2u(u2f2(uB.y)), mul2(q01B, f2u(u2f2(uB.x))));
            unpack2(tB, ta, tb);
            float pB = __expf(ta + tb);
            sumB += pB;
            u64 p2B = pack2(pB, pB);
            aB01 = fma2(p2B, f2u(u2f2(uB.z)), aB01);
            aB23 = fma2(p2B, f2u(u2f2(uB.w)), aB23);
        }
        float invA = 1.f / sumA, invB = 1.f / sumB;
        float oa, ob, oc, od;
        unpack2(aA01, oa, ob); unpack2(aA23, oc, od);
        *(float4*)(so + lane * 32 + 4 * h) = make_float4(oa * invA, ob * invA, oc * invA, od * invA);
        unpack2(aB01, oa, ob); unpack2(aB23, oc, od);
        *(float4*)(so + 1024 + lane * 32 + 4 * h) = make_float4(oa * invB, ob * invB, oc * invB, od * invB);
        __syncwarp();   // done reading skv before next head overwrites
    }

    // ---- reload o rows (own rows only), shared-weight W0 GEMV for both tiles ----
    u64 o2A[16], o2B[16];
    {
        const ulonglong2* oa = (const ulonglong2*)(so + lane * 32);
        const ulonglong2* ob = (const ulonglong2*)(so + 1024 + lane * 32);
#pragma unroll
        for (int j = 0; j < 8; j++) {
            ulonglong2 va = oa[j]; o2A[2*j] = va.x; o2A[2*j+1] = va.y;
            ulonglong2 vb = ob[j]; o2B[2*j] = vb.x; o2B[2*j+1] = vb.y;
        }
    }

#pragma unroll
    for (int j = 0; j < 32; j += 4) {
        float4 rA, rB;
        float* pa = &rA.x; float* pb = &rB.x;
#pragma unroll
        for (int jj = 0; jj < 4; jj++) {
            const ulonglong2* wr = (const ulonglong2*)(sW0 + (j + jj) * 32);
            u64 accA = 0, accB = 0;
#pragma unroll
            for (int m = 0; m < 8; m++) {
                ulonglong2 ww = wr[m];
                accA = fma2(o2A[2*m+1], ww.y, fma2(o2A[2*m], ww.x, accA));
                accB = fma2(o2B[2*m+1], ww.y, fma2(o2B[2*m], ww.x, accB));
            }
            float xa, xb;
            unpack2(accA, xa, xb); pa[jj] = xa + xb;
            unpack2(accB, xa, xb); pb[jj] = xa + xb;
        }
        *(float4*)(ogA + lane * 32 + j) = rA;
        *(float4*)(ogB + lane * 32 + j) = rB;
    }
}

// ---------------------------------------------------------------------------
// x-branch full warp attention (fp32, fused residual+LN+sigmoid) — tiny grid.
// ---------------------------------------------------------------------------
__device__ __forceinline__ void warp_attn_full(
    int lane,
    const float* __restrict__ eg, float* __restrict__ og,
    const float* __restrict__ sW, const float* __restrict__ sW0,
    const float* __restrict__ sgb, float* __restrict__ skv)
{
    u64 e2[16];
    {
        const ulonglong2* ep = (const ulonglong2*)(eg + lane * 32);
#pragma unroll
        for (int j = 0; j < 8; j++) { ulonglong2 v = ep[j]; e2[2*j] = v.x; e2[2*j+1] = v.y; }
    }
    float rr[32];
#pragma unroll
    for (int j = 0; j < 16; j++) unpack2(e2[j], rr[2*j], rr[2*j+1]);

#pragma unroll 1
    for (int h = 0; h < 8; h++) {
        float q[4], kk[4], vv[4];
#pragma unroll
        for (int d = 0; d < 4; d++) {
            const ulonglong2* wq = (const ulonglong2*)(sW + (d * 24 + h)      * 32);
            const ulonglong2* wk = (const ulonglong2*)(sW + (d * 24 + 8 + h)  * 32);
            const ulonglong2* wv = (const ulonglong2*)(sW + (d * 24 + 16 + h) * 32);
            u64 aq = 0, ak = 0, av = 0;
#pragma unroll
            for (int j = 0; j < 8; j++) {
                ulonglong2 ww;
                ww = wq[j]; aq = fma2(e2[2*j+1], ww.y, fma2(e2[2*j], ww.x, aq));
                ww = wk[j]; ak = fma2(e2[2*j+1], ww.y, fma2(e2[2*j], ww.x, ak));
                ww = wv[j]; av = fma2(e2[2*j+1], ww.y, fma2(e2[2*j], ww.x, av));
            }
            float a, b;
            unpack2(aq, a, b); q[d]  = (a + b) * 0.5f;
            unpack2(ak, a, b); kk[d] = a + b;
            unpack2(av, a, b); vv[d] = a + b;
        }
        *(float4*)(skv + lane * 12)     = make_float4(kk[0], kk[1], kk[2], kk[3]);
        *(float4*)(skv + lane * 12 + 4) = make_float4(vv[0], vv[1], vv[2], vv[3]);
        u64 q01 = pack2(q[0], q[1]), q23 = pack2(q[2], q[3]);
        __syncwarp();

        float sum = 0.f;
        u64 a01 = 0, a23 = 0;
#pragma unroll
        for (int s = 0; s < 32; s++) {
            ulonglong2 k2 = *(const ulonglong2*)(skv + s * 12);
            ulonglong2 v2 = *(const ulonglong2*)(skv + s * 12 + 4);
            u64 t = fma2(q23, k2.y, mul2(q01, k2.x));
            float ta, tb; unpack2(t, ta, tb);
            float p = __expf(ta + tb);
            sum += p;
            u64 p2 = pack2(p, p);
            a01 = fma2(p2, v2.x, a01);
            a23 = fma2(p2, v2.y, a23);
        }
        __syncwarp();
        float inv = 1.f / sum;
        float oa, ob, oc, od;
        unpack2(a01, oa, ob); unpack2(a23, oc, od);
        u64 o01 = pack2(oa * inv, ob * inv), o23 = pack2(oc * inv, od * inv);

        const float* w0h = sW0 + 4 * h;
#pragma unroll
        for (int j = 0; j < 32; j += 2) {
            ulonglong2 wa = *(const ulonglong2*)(w0h + j * 32);
            ulonglong2 wb = *(const ulonglong2*)(w0h + (j + 1) * 32);
            u64 ra = fma2(o23, wa.y, mul2(o01, wa.x));
            u64 rb = fma2(o23, wb.y, mul2(o01, wb.x));
            float xa, xb;
            unpack2(ra, xa, xb); rr[j]     += xa + xb;
            unpack2(rb, xa, xb); rr[j + 1] += xa + xb;
        }
    }

    float s1 = 0.f;
#pragma unroll
    for (int j = 0; j < 32; j++) s1 += rr[j];
    float mu = s1 * 0.03125f;
    float sq = 0.f;
#pragma unroll
    for (int j = 0; j < 32; j++) { float d = rr[j] - mu; sq = fmaf(d, d, sq); }
    float rstd = rsqrtf(sq * 0.03125f + 1e-5f);

    float* po = og + lane * 32;
#pragma unroll
    for (int j = 0; j < 32; j += 4) {
        float4 v;
        v.x = sigmoid_((rr[j]     - mu) * rstd * sgb[j]     + sgb[32 + j]);
        v.y = sigmoid_((rr[j + 1] - mu) * rstd * sgb[j + 1] + sgb[33 + j]);
        v.z = sigmoid_((rr[j + 2] - mu) * rstd * sgb[j + 2] + sgb[34 + j]);
        v.w = sigmoid_((rr[j + 3] - mu) * rstd * sgb[j + 3] + sgb[35 + j]);
        *(float4*)(po + j) = v;
    }
}

#define WX 4
__global__ void __launch_bounds__(WX * 32) k_attn_x(
    const float* __restrict__ Wqvk, const float* __restrict__ W0,
    const float* __restrict__ g, const float* __restrict__ b)
{
    extern __shared__ float smx[];
    float* sW3  = smx;             // 3 * 3072
    float* sW03 = smx + 9216;      // 3 * 1024
    float* sgb  = smx + 12288;     // 64
    float* tiles = smx + 12352;    // WX * 384

    int tid = threadIdx.x;
    int w = tid >> 5, lane = tid & 31;
    for (int k = tid; k < 2304; k += WX * 32) ((float4*)sW3)[k]  = ((const float4*)Wqvk)[k];
    for (int k = tid; k < 768;  k += WX * 32) ((float4*)sW03)[k] = ((const float4*)W0)[k];
    if (tid < 32) { sgb[tid] = g[tid]; sgb[32 + tid] = b[tid]; }
    __syncthreads();

    int lin = blockIdx.x * WX + w;   // b*3 + c
    int bb = lin / 3, c = lin % 3;
    const float* eg = g_emb + (((size_t)bb * 3 + 2) * 32 + 31) * 1024;
    float* og = g_sg2 + (size_t)lin * 1024;
    warp_attn_full(lane, eg, og, sW3 + c * 3072, sW03 + c * 1024, sgb, tiles + w * 384);
}

// ---------------------------------------------------------------------------
// K4: gate_y = sigmoid(LN(emb + proj)); out = sg2 * gate_y * x.
// ---------------------------------------------------------------------------
__global__ void __launch_bounds__(256) k_final(const float* __restrict__ x,
                                               const float* __restrict__ gam,
                                               const float* __restrict__ bet,
                                               float* __restrict__ out)
{
    __shared__ float gs[32 * 33];
    __shared__ float ss[32];
    int bct = blockIdx.x;
    int t = bct & 31;
    int bc = bct >> 5;
    int tid = threadIdx.x;

    int i = tid >> 3, j0 = (tid & 7) * 4;
    size_t base = ((size_t)bc * 32 + i) * 1024 + t * 32 + j0;
    float4 pv = *(const float4*)(g_sig + base);
    float4 ev = *(const float4*)(g_emb + base);
    float4 v;
    v.x = pv.x + ev.x; v.y = pv.y + ev.y; v.z = pv.z + ev.z; v.w = pv.w + ev.w;

    float s1 = v.x + v.y + v.z + v.w;
    float s2 = fmaf(v.x, v.x, fmaf(v.y, v.y, fmaf(v.z, v.z, v.w * v.w)));
#pragma unroll
    for (int m = 1; m < 8; m <<= 1) {
        s1 += __shfl_xor_sync(0xffffffffu, s1, m);
        s2 += __shfl_xor_sync(0xffffffffu, s2, m);
    }
    float mu = s1 * 0.03125f;
    float var = fmaf(-mu, mu, s2 * 0.03125f);
    float rstd = rsqrtf(var + 1e-5f);

    float4 gm = *(const float4*)(gam + j0);
    float4 bt = *(const float4*)(bet + j0);
    gs[i * 33 + j0 + 0] = sigmoid_((v.x - mu) * rstd * gm.x + bt.x);
    gs[i * 33 + j0 + 1] = sigmoid_((v.y - mu) * rstd * gm.y + bt.y);
    gs[i * 33 + j0 + 2] = sigmoid_((v.z - mu) * rstd * gm.z + bt.z);
    gs[i * 33 + j0 + 3] = sigmoid_((v.w - mu) * rstd * gm.w + bt.w);
    if (tid < 32) ss[tid] = g_sg2[(size_t)bc * 1024 + tid * 32 + t];
    __syncthreads();

    float4 xv = ((const float4*)(x + (size_t)bct * 1024))[tid];
    int jj = tid >> 3, i0 = (tid & 7) * 4;
    float4 ov;
    ov.x = ss[i0 + 0] * gs[(i0 + 0) * 33 + jj] * xv.x;
    ov.y = ss[i0 + 1] * gs[(i0 + 1) * 33 + jj] * xv.y;
    ov.z = ss[i0 + 2] * gs[(i0 + 2) * 33 + jj] * xv.z;
    ov.w = ss[i0 + 3] * gs[(i0 + 3) * 33 + jj] * xv.w;
    ((float4*)(out + (size_t)bct * 1024))[tid] = ov;
}

// ---------------------------------------------------------------------------
extern "C" void kernel_launch(void* const* d_in, const int* in_sizes, int n_in,
                              void* d_out, int out_size)
{
    const float* x   = (const float*)d_in[0];
    const float* pos = (const float*)d_in[1];
    const float* Wqy = (const float*)d_in[2];
    const float* W0y = (const float*)d_in[3];
    const float* gy  = (const float*)d_in[4];
    const float* by  = (const float*)d_in[5];
    const float* Wqx = (const float*)d_in[6];
    const float* W0x = (const float*)d_in[7];
    const float* gx  = (const float*)d_in[8];
    const float* bx  = (const float*)d_in[9];
    float* out = (float*)d_out;

    int B = in_sizes[0] / 98304;  // 3*32*32*32

    const int SMEM_Y = (4096 + WY * 256 + WY * 2048) * 4;   // 53,248 B
    const int SMEM_X = (12352 + WX * 384) * 4;
    cudaFuncSetAttribute(k_attn_y2, cudaFuncAttributeMaxDynamicSharedMemorySize, SMEM_Y);
    cudaFuncSetAttribute(k_attn_x, cudaFuncAttributeMaxDynamicSharedMemorySize, SMEM_X);

    int nY = B * 12;          // total CTAs for y-branch (4 CTAs per (b,c))
    int h1 = nY / 2;

    k_emb<<<B * 96, 256>>>(x, pos);
    k_attn_x<<<(B * 3) / WX, WX * 32, SMEM_X>>>(Wqx, W0x, gx, bx);
    k_attn_y2<<<h1, WY * 32, SMEM_Y>>>(Wqy, W0y, 0);       // split for ncu visibility
    k_attn_y2<<<nY - h1, WY * 32, SMEM_Y>>>(Wqy, W0y, h1);
    k_final<<<B * 96, 256>>>(x, gy, by, out);
}

// round 6
// speedup vs baseline: 1.6356x; 1.4757x over previous
#include <cuda_runtime.h>
#include <cuda_fp16.h>

typedef unsigned long long u64;

#define B_MAX 256

__device__ float g_emb[B_MAX * 3 * 32 * 32 * 32];  // [b][c][i][t][j]
__device__ float g_sig[B_MAX * 3 * 32 * 32 * 32];  // y-branch RAW W0 projection
__device__ float g_sg2[B_MAX * 3 * 32 * 32];       // sigmoid(LN(x-branch))

// ---------------- packed f32x2 helpers ----------------
__device__ __forceinline__ u64 pack2(float lo, float hi) {
    u64 r; asm("mov.b64 %0, {%1, %2};" : "=l"(r) : "f"(lo), "f"(hi)); return r;
}
__device__ __forceinline__ void unpack2(u64 v, float& lo, float& hi) {
    asm("mov.b64 {%0, %1}, %2;" : "=f"(lo), "=f"(hi) : "l"(v));
}
__device__ __forceinline__ u64 fma2(u64 a, u64 b, u64 c) {
    u64 d; asm("fma.rn.f32x2 %0, %1, %2, %3;" : "=l"(d) : "l"(a), "l"(b), "l"(c)); return d;
}
__device__ __forceinline__ u64 mul2(u64 a, u64 b) {
    u64 d; asm("mul.rn.f32x2 %0, %1, %2;" : "=l"(d) : "l"(a), "l"(b)); return d;
}
__device__ __forceinline__ u64 f2u(float2 v) {
    u64 r; asm("mov.b64 %0, {%1, %2};" : "=l"(r) : "f"(v.x), "f"(v.y)); return r;
}
__device__ __forceinline__ unsigned h2u(__half2 h) { return *(unsigned*)&h; }
__device__ __forceinline__ float2 u2f2(unsigned u) { __half2 h = *(__half2*)&u; return __half22float2(h); }
__device__ __forceinline__ float sigmoid_(float v) { return 1.0f / (1.0f + __expf(-v)); }

// ---------------------------------------------------------------------------
// K1 v2: emb[b,c,i,t,j] = sum_d x[b,c,t,d,i] * pos_y[c,j,d]
// One CTA per (b,c): pos staged ONCE as ps[d][j] (conflict-free LDS.128 reads),
// x tiles staged as xs[d][i] stride-33 (conflict-free scalar load/store).
// Two t-tiles per iteration amortize ps reads.
// ---------------------------------------------------------------------------
__global__ void __launch_bounds__(256) k_emb2(const float* __restrict__ x,
                                              const float* __restrict__ pos)
{
    __shared__ float ps[32 * 36];      // ps[d][j]
    __shared__ float xs[2][32 * 33];   // xs[tile][d][i]

    int bc = blockIdx.x;
    int c = bc % 3;
    int tid = threadIdx.x;

    // stage pos transposed: pos[c][j][d] -> ps[d][j]
    {
        float4 pv = ((const float4*)(pos + c * 1024))[tid];
        int j = tid >> 3, d0 = (tid & 7) * 4;
        ps[(d0 + 0) * 36 + j] = pv.x;
        ps[(d0 + 1) * 36 + j] = pv.y;
        ps[(d0 + 2) * 36 + j] = pv.z;
        ps[(d0 + 3) * 36 + j] = pv.w;
    }

    const float* xb = x + (size_t)bc * 32768;
    float* ob = g_emb + (size_t)bc * 32768;
    int i  = tid >> 3, j0 = (tid & 7) * 4;   // compute mapping
    int dd = tid >> 3, i4 = (tid & 7) * 4;   // staging mapping

    for (int tg = 0; tg < 16; tg++) {
        float4 xv0 = ((const float4*)(xb + (size_t)(2 * tg)     * 1024))[tid];
        float4 xv1 = ((const float4*)(xb + (size_t)(2 * tg + 1) * 1024))[tid];
        __syncthreads();   // previous group's compute done before overwrite
        xs[0][dd * 33 + i4 + 0] = xv0.x; xs[0][dd * 33 + i4 + 1] = xv0.y;
        xs[0][dd * 33 + i4 + 2] = xv0.z; xs[0][dd * 33 + i4 + 3] = xv0.w;
        xs[1][dd * 33 + i4 + 0] = xv1.x; xs[1][dd * 33 + i4 + 1] = xv1.y;
        xs[1][dd * 33 + i4 + 2] = xv1.z; xs[1][dd * 33 + i4 + 3] = xv1.w;
        __syncthreads();

        u64 a00 = 0, a01 = 0, a10 = 0, a11 = 0;
#pragma unroll
        for (int d = 0; d < 32; d++) {
            ulonglong2 p = *(const ulonglong2*)(ps + d * 36 + j0);
            float x0 = xs[0][d * 33 + i];
            float x1 = xs[1][d * 33 + i];
            u64 x0p = pack2(x0, x0), x1p = pack2(x1, x1);
            a00 = fma2(x0p, p.x, a00); a01 = fma2(x0p, p.y, a01);
            a10 = fma2(x1p, p.x, a10); a11 = fma2(x1p, p.y, a11);
        }
        float b0, b1, b2, b3;
        unpack2(a00, b0, b1); unpack2(a01, b2, b3);
        *(float4*)(ob + (size_t)i * 1024 + (2 * tg) * 32 + j0) = make_float4(b0, b1, b2, b3);
        unpack2(a10, b0, b1); unpack2(a11, b2, b3);
        *(float4*)(ob + (size_t)i * 1024 + (2 * tg + 1) * 32 + j0) = make_float4(b0, b1, b2, b3);
    }
}

// ---------------------------------------------------------------------------
// K3: y-branch, TWO tiles per warp (UNCHANGED from R5 — measured 199.5us/half)
// ---------------------------------------------------------------------------
#define WY 4
__global__ void __launch_bounds__(WY * 32, 4) k_attn_y2(
    const float* __restrict__ Wqvk, const float* __restrict__ W0, int base)
{
    extern __shared__ float sm[];
    float* sW  = sm;
    float* sW0 = sm + 3072;

    int tid = threadIdx.x;
    int w = tid >> 5, lane = tid & 31;
    float* skv = sm + 4096 + w * 256;
    float* so  = sm + 5120 + w * 2048;

    int cid = base + blockIdx.x;
    int bc = cid >> 2;
    int ib = cid & 3;
    int c = bc % 3;

    for (int k = tid; k < 768; k += WY * 32) ((float4*)sW)[k]  = ((const float4*)(Wqvk + c * 3072))[k];
    for (int k = tid; k < 256; k += WY * 32) ((float4*)sW0)[k] = ((const float4*)(W0 + c * 1024))[k];
    __syncthreads();

    int i0 = ib * 8 + w * 2;
    const float* egA = g_emb + ((size_t)bc * 32 + i0) * 1024;
    const float* egB = egA + 1024;
    float* ogA = g_sig + ((size_t)bc * 32 + i0) * 1024;
    float* ogB = ogA + 1024;

    u64 e2A[16], e2B[16];
    {
        const ulonglong2* ea = (const ulonglong2*)(egA + lane * 32);
        const ulonglong2* eb = (const ulonglong2*)(egB + lane * 32);
#pragma unroll
        for (int j = 0; j < 8; j++) {
            ulonglong2 va = ea[j]; e2A[2*j] = va.x; e2A[2*j+1] = va.y;
            ulonglong2 vb = eb[j]; e2B[2*j] = vb.x; e2B[2*j+1] = vb.y;
        }
    }

#pragma unroll 1
    for (int h = 0; h < 8; h++) {
        float qA[4], kA[4], vA[4], qB[4], kB[4], vB[4];
#pragma unroll
        for (int d = 0; d < 4; d++) {
            const ulonglong2* wq = (const ulonglong2*)(sW + (d * 24 + h)      * 32);
            const ulonglong2* wk = (const ulonglong2*)(sW + (d * 24 + 8 + h)  * 32);
            const ulonglong2* wv = (const ulonglong2*)(sW + (d * 24 + 16 + h) * 32);
            u64 aqA = 0, akA = 0, avA = 0, aqB = 0, akB = 0, avB = 0;
#pragma unroll
            for (int j = 0; j < 8; j++) {
                ulonglong2 ww;
                ww = wq[j];
                aqA = fma2(e2A[2*j+1], ww.y, fma2(e2A[2*j], ww.x, aqA));
                aqB = fma2(e2B[2*j+1], ww.y, fma2(e2B[2*j], ww.x, aqB));
                ww = wk[j];
                akA = fma2(e2A[2*j+1], ww.y, fma2(e2A[2*j], ww.x, akA));
                akB = fma2(e2B[2*j+1], ww.y, fma2(e2B[2*j], ww.x, akB));
                ww = wv[j];
                avA = fma2(e2A[2*j+1], ww.y, fma2(e2A[2*j], ww.x, avA));
                avB = fma2(e2B[2*j+1], ww.y, fma2(e2B[2*j], ww.x, avB));
            }
            float a, b;
            unpack2(aqA, a, b); qA[d] = (a + b) * 0.5f;
            unpack2(akA, a, b); kA[d] = a + b;
            unpack2(avA, a, b); vA[d] = a + b;
            unpack2(aqB, a, b); qB[d] = (a + b) * 0.5f;
            unpack2(akB, a, b); kB[d] = a + b;
            unpack2(avB, a, b); vB[d] = a + b;
        }
        {
            uint4 uA, uB;
            uA.x = h2u(__floats2half2_rn(kA[0], kA[1]));
            uA.y = h2u(__floats2half2_rn(kA[2], kA[3]));
            uA.z = h2u(__floats2half2_rn(vA[0], vA[1]));
            uA.w = h2u(__floats2half2_rn(vA[2], vA[3]));
            uB.x = h2u(__floats2half2_rn(kB[0], kB[1]));
            uB.y = h2u(__floats2half2_rn(kB[2], kB[3]));
            uB.z = h2u(__floats2half2_rn(vB[0], vB[1]));
            uB.w = h2u(__floats2half2_rn(vB[2], vB[3]));
            *(uint4*)(skv + lane * 8)     = uA;
            *(uint4*)(skv + lane * 8 + 4) = uB;
        }
        u64 q01A = pack2(qA[0], qA[1]), q23A = pack2(qA[2], qA[3]);
        u64 q01B = pack2(qB[0], qB[1]), q23B = pack2(qB[2], qB[3]);
        __syncwarp();

        float sumA = 0.f, sumB = 0.f;
        u64 aA01 = 0, aA23 = 0, aB01 = 0, aB23 = 0;
#pragma unroll 8
        for (int s = 0; s < 32; s++) {
            uint4 uA = *(uint4*)(skv + s * 8);
            uint4 uB = *(uint4*)(skv + s * 8 + 4);
            u64 tA = fma2(q23A, f2u(u2f2(uA.y)), mul2(q01A, f2u(u2f2(uA.x))));
            float ta, tb; unpack2(tA, ta, tb);
            float pA = __expf(ta + tb);
            sumA += pA;
            u64 p2A = pack2(pA, pA);
            aA01 = fma2(p2A, f2u(u2f2(uA.z)), aA01);
            aA23 = fma2(p2A, f2u(u2f2(uA.w)), aA23);
            u64 tB = fma2(q23B, f2u(u2f2(uB.y)), mul2(q01B, f2u(u2f2(uB.x))));
            unpack2(tB, ta, tb);
            float pB = __expf(ta + tb);
            sumB += pB;
            u64 p2B = pack2(pB, pB);
            aB01 = fma2(p2B, f2u(u2f2(uB.z)), aB01);
            aB23 = fma2(p2B, f2u(u2f2(uB.w)), aB23);
        }
        float invA = 1.f / sumA, invB = 1.f / sumB;
        float oa, ob, oc, od;
        unpack2(aA01, oa, ob); unpack2(aA23, oc, od);
        *(float4*)(so + lane * 32 + 4 * h) = make_float4(oa * invA, ob * invA, oc * invA, od * invA);
        unpack2(aB01, oa, ob); unpack2(aB23, oc, od);
        *(float4*)(so + 1024 + lane * 32 + 4 * h) = make_float4(oa * invB, ob * invB, oc * invB, od * invB);
        __syncwarp();
    }

    u64 o2A[16], o2B[16];
    {
        const ulonglong2* oa = (const ulonglong2*)(so + lane * 32);
        const ulonglong2* ob = (const ulonglong2*)(so + 1024 + lane * 32);
#pragma unroll
        for (int j = 0; j < 8; j++) {
            ulonglong2 va = oa[j]; o2A[2*j] = va.x; o2A[2*j+1] = va.y;
            ulonglong2 vb = ob[j]; o2B[2*j] = vb.x; o2B[2*j+1] = vb.y;
        }
    }

#pragma unroll
    for (int j = 0; j < 32; j += 4) {
        float4 rA, rB;
        float* pa = &rA.x; float* pb = &rB.x;
#pragma unroll
        for (int jj = 0; jj < 4; jj++) {
            const ulonglong2* wr = (const ulonglong2*)(sW0 + (j + jj) * 32);
            u64 accA = 0, accB = 0;
#pragma unroll
            for (int m = 0; m < 8; m++) {
                ulonglong2 ww = wr[m];
                accA = fma2(o2A[2*m+1], ww.y, fma2(o2A[2*m], ww.x, accA));
                accB = fma2(o2B[2*m+1], ww.y, fma2(o2B[2*m], ww.x, accB));
            }
            float xa, xb;
            unpack2(accA, xa, xb); pa[jj] = xa + xb;
            unpack2(accB, xa, xb); pb[jj] = xa + xb;
        }
        *(float4*)(ogA + lane * 32 + j) = rA;
        *(float4*)(ogB + lane * 32 + j) = rB;
    }
}

// ---------------------------------------------------------------------------
// x-branch full warp attention (fp32, fused residual+LN+sigmoid)
// ---------------------------------------------------------------------------
__device__ __forceinline__ void warp_attn_full(
    int lane,
    const float* __restrict__ eg, float* __restrict__ og,
    const float* __restrict__ sW, const float* __restrict__ sW0,
    const float* __restrict__ sgb, float* __restrict__ skv)
{
    u64 e2[16];
    {
        const ulonglong2* ep = (const ulonglong2*)(eg + lane * 32);
#pragma unroll
        for (int j = 0; j < 8; j++) { ulonglong2 v = ep[j]; e2[2*j] = v.x; e2[2*j+1] = v.y; }
    }
    float rr[32];
#pragma unroll
    for (int j = 0; j < 16; j++) unpack2(e2[j], rr[2*j], rr[2*j+1]);

#pragma unroll 1
    for (int h = 0; h < 8; h++) {
        float q[4], kk[4], vv[4];
#pragma unroll
        for (int d = 0; d < 4; d++) {
            const ulonglong2* wq = (const ulonglong2*)(sW + (d * 24 + h)      * 32);
            const ulonglong2* wk = (const ulonglong2*)(sW + (d * 24 + 8 + h)  * 32);
            const ulonglong2* wv = (const ulonglong2*)(sW + (d * 24 + 16 + h) * 32);
            u64 aq = 0, ak = 0, av = 0;
#pragma unroll
            for (int j = 0; j < 8; j++) {
                ulonglong2 ww;
                ww = wq[j]; aq = fma2(e2[2*j+1], ww.y, fma2(e2[2*j], ww.x, aq));
                ww = wk[j]; ak = fma2(e2[2*j+1], ww.y, fma2(e2[2*j], ww.x, ak));
                ww = wv[j]; av = fma2(e2[2*j+1], ww.y, fma2(e2[2*j], ww.x, av));
            }
            float a, b;
            unpack2(aq, a, b); q[d]  = (a + b) * 0.5f;
            unpack2(ak, a, b); kk[d] = a + b;
            unpack2(av, a, b); vv[d] = a + b;
        }
        *(float4*)(skv + lane * 12)     = make_float4(kk[0], kk[1], kk[2], kk[3]);
        *(float4*)(skv + lane * 12 + 4) = make_float4(vv[0], vv[1], vv[2], vv[3]);
        u64 q01 = pack2(q[0], q[1]), q23 = pack2(q[2], q[3]);
        __syncwarp();

        float sum = 0.f;
        u64 a01 = 0, a23 = 0;
#pragma unroll
        for (int s = 0; s < 32; s++) {
            ulonglong2 k2 = *(const ulonglong2*)(skv + s * 12);
            ulonglong2 v2 = *(const ulonglong2*)(skv + s * 12 + 4);
            u64 t = fma2(q23, k2.y, mul2(q01, k2.x));
            float ta, tb; unpack2(t, ta, tb);
            float p = __expf(ta + tb);
            sum += p;
            u64 p2 = pack2(p, p);
            a01 = fma2(p2, v2.x, a01);
            a23 = fma2(p2, v2.y, a23);
        }
        __syncwarp();
        float inv = 1.f / sum;
        float oa, ob, oc, od;
        unpack2(a01, oa, ob); unpack2(a23, oc, od);
        u64 o01 = pack2(oa * inv, ob * inv), o23 = pack2(oc * inv, od * inv);

        const float* w0h = sW0 + 4 * h;
#pragma unroll
        for (int j = 0; j < 32; j += 2) {
            ulonglong2 wa = *(const ulonglong2*)(w0h + j * 32);
            ulonglong2 wb = *(const ulonglong2*)(w0h + (j + 1) * 32);
            u64 ra = fma2(o23, wa.y, mul2(o01, wa.x));
            u64 rb = fma2(o23, wb.y, mul2(o01, wb.x));
            float xa, xb;
            unpack2(ra, xa, xb); rr[j]     += xa + xb;
            unpack2(rb, xa, xb); rr[j + 1] += xa + xb;
        }
    }

    float s1 = 0.f;
#pragma unroll
    for (int j = 0; j < 32; j++) s1 += rr[j];
    float mu = s1 * 0.03125f;
    float sq = 0.f;
#pragma unroll
    for (int j = 0; j < 32; j++) { float d = rr[j] - mu; sq = fmaf(d, d, sq); }
    float rstd = rsqrtf(sq * 0.03125f + 1e-5f);

    float* po = og + lane * 32;
#pragma unroll
    for (int j = 0; j < 32; j += 4) {
        float4 v;
        v.x = sigmoid_((rr[j]     - mu) * rstd * sgb[j]     + sgb[32 + j]);
        v.y = sigmoid_((rr[j + 1] - mu) * rstd * sgb[j + 1] + sgb[33 + j]);
        v.z = sigmoid_((rr[j + 2] - mu) * rstd * sgb[j + 2] + sgb[34 + j]);
        v.w = sigmoid_((rr[j + 3] - mu) * rstd * sgb[j + 3] + sgb[35 + j]);
        *(float4*)(po + j) = v;
    }
}

// ---------------------------------------------------------------------------
// K2 v2: x-branch grouped by c — CTA loads only its c's weights (16 KB).
// CTA = (c, 4 consecutive b). Warp w handles b = bq*4 + w.
// ---------------------------------------------------------------------------
__global__ void __launch_bounds__(128) k_attn_x2(
    const float* __restrict__ Wqvk, const float* __restrict__ W0,
    const float* __restrict__ g, const float* __restrict__ b, int nb4)
{
    __shared__ float sW[3072];
    __shared__ float sW0[1024];
    __shared__ float sgb[64];
    __shared__ float tiles[4 * 384];

    int tid = threadIdx.x;
    int w = tid >> 5, lane = tid & 31;
    int c  = blockIdx.x / nb4;
    int bq = blockIdx.x % nb4;

    for (int k = tid; k < 768; k += 128) ((float4*)sW)[k]  = ((const float4*)(Wqvk + c * 3072))[k];
    for (int k = tid; k < 256; k += 128) ((float4*)sW0)[k] = ((const float4*)(W0 + c * 1024))[k];
    if (tid < 32) { sgb[tid] = g[tid]; sgb[32 + tid] = b[tid]; }
    __syncthreads();

    int bb = bq * 4 + w;
    const float* eg = g_emb + (((size_t)bb * 3 + 2) * 32 + 31) * 1024;
    float* og = g_sg2 + ((size_t)bb * 3 + c) * 1024;
    warp_attn_full(lane, eg, og, sW, sW0, sgb, tiles + w * 384);
}

// ---------------------------------------------------------------------------
// K4: gate_y = sigmoid(LN(emb + proj)); out = sg2 * gate_y * x. (UNCHANGED)
// ---------------------------------------------------------------------------
__global__ void __launch_bounds__(256) k_final(const float* __restrict__ x,
                                               const float* __restrict__ gam,
                                               const float* __restrict__ bet,
                                               float* __restrict__ out)
{
    __shared__ float gs[32 * 33];
    __shared__ float ss[32];
    int bct = blockIdx.x;
    int t = bct & 31;
    int bc = bct >> 5;
    int tid = threadIdx.x;

    int i = tid >> 3, j0 = (tid & 7) * 4;
    size_t base = ((size_t)bc * 32 + i) * 1024 + t * 32 + j0;
    float4 pv = *(const float4*)(g_sig + base);
    float4 ev = *(const float4*)(g_emb + base);
    float4 v;
    v.x = pv.x + ev.x; v.y = pv.y + ev.y; v.z = pv.z + ev.z; v.w = pv.w + ev.w;

    float s1 = v.x + v.y + v.z + v.w;
    float s2 = fmaf(v.x, v.x, fmaf(v.y, v.y, fmaf(v.z, v.z, v.w * v.w)));
#pragma unroll
    for (int m = 1; m < 8; m <<= 1) {
        s1 += __shfl_xor_sync(0xffffffffu, s1, m);
        s2 += __shfl_xor_sync(0xffffffffu, s2, m);
    }
    float mu = s1 * 0.03125f;
    float var = fmaf(-mu, mu, s2 * 0.03125f);
    float rstd = rsqrtf(var + 1e-5f);

    float4 gm = *(const float4*)(gam + j0);
    float4 bt = *(const float4*)(bet + j0);
    gs[i * 33 + j0 + 0] = sigmoid_((v.x - mu) * rstd * gm.x + bt.x);
    gs[i * 33 + j0 + 1] = sigmoid_((v.y - mu) * rstd * gm.y + bt.y);
    gs[i * 33 + j0 + 2] = sigmoid_((v.z - mu) * rstd * gm.z + bt.z);
    gs[i * 33 + j0 + 3] = sigmoid_((v.w - mu) * rstd * gm.w + bt.w);
    if (tid < 32) ss[tid] = g_sg2[(size_t)bc * 1024 + tid * 32 + t];
    __syncthreads();

    float4 xv = ((const float4*)(x + (size_t)bct * 1024))[tid];
    int jj = tid >> 3, i0 = (tid & 7) * 4;
    float4 ov;
    ov.x = ss[i0 + 0] * gs[(i0 + 0) * 33 + jj] * xv.x;
    ov.y = ss[i0 + 1] * gs[(i0 + 1) * 33 + jj] * xv.y;
    ov.z = ss[i0 + 2] * gs[(i0 + 2) * 33 + jj] * xv.z;
    ov.w = ss[i0 + 3] * gs[(i0 + 3) * 33 + jj] * xv.w;
    ((float4*)(out + (size_t)bct * 1024))[tid] = ov;
}

// ---------------------------------------------------------------------------
extern "C" void kernel_launch(void* const* d_in, const int* in_sizes, int n_in,
                              void* d_out, int out_size)
{
    const float* x   = (const float*)d_in[0];
    const float* pos = (const float*)d_in[1];
    const float* Wqy = (const float*)d_in[2];
    const float* W0y = (const float*)d_in[3];
    const float* gy  = (const float*)d_in[4];
    const float* by  = (const float*)d_in[5];
    const float* Wqx = (const float*)d_in[6];
    const float* W0x = (const float*)d_in[7];
    const float* gx  = (const float*)d_in[8];
    const float* bx  = (const float*)d_in[9];
    float* out = (float*)d_out;

    int B = in_sizes[0] / 98304;  // 3*32*32*32

    const int SMEM_Y = (4096 + WY * 256 + WY * 2048) * 4;   // 53,248 B
    cudaFuncSetAttribute(k_attn_y2, cudaFuncAttributeMaxDynamicSharedMemorySize, SMEM_Y);

    int nY = B * 12;
    int h1 = nY / 2;
    int nb4 = B / 4;

    k_emb2<<<B * 3, 256>>>(x, pos);
    k_attn_x2<<<3 * nb4, 128>>>(Wqx, W0x, gx, bx, nb4);
    k_attn_y2<<<h1, WY * 32, SMEM_Y>>>(Wqy, W0y, 0);
    k_attn_y2<<<nY - h1, WY * 32, SMEM_Y>>>(Wqy, W0y, h1);
    k_final<<<B * 96, 256>>>(x, gy, by, out);
}

// round 7
// speedup vs baseline: 1.7991x; 1.1000x over previous
#include <cuda_runtime.h>
#include <cuda_fp16.h>

typedef unsigned long long u64;

#define B_MAX 256

__device__ float g_emb[B_MAX * 3 * 32 * 32 * 32];  // [b][c][i][t][j]
__device__ float g_sig[B_MAX * 3 * 32 * 32 * 32];  // y-branch RAW W0 projection
__device__ float g_sg2[B_MAX * 3 * 32 * 32];       // sigmoid(LN(x-branch))

// ---------------- packed f32x2 helpers ----------------
__device__ __forceinline__ u64 pack2(float lo, float hi) {
    u64 r; asm("mov.b64 %0, {%1, %2};" : "=l"(r) : "f"(lo), "f"(hi)); return r;
}
__device__ __forceinline__ void unpack2(u64 v, float& lo, float& hi) {
    asm("mov.b64 {%0, %1}, %2;" : "=f"(lo), "=f"(hi) : "l"(v));
}
__device__ __forceinline__ u64 fma2(u64 a, u64 b, u64 c) {
    u64 d; asm("fma.rn.f32x2 %0, %1, %2, %3;" : "=l"(d) : "l"(a), "l"(b), "l"(c)); return d;
}
__device__ __forceinline__ u64 mul2(u64 a, u64 b) {
    u64 d; asm("mul.rn.f32x2 %0, %1, %2;" : "=l"(d) : "l"(a), "l"(b)); return d;
}
__device__ __forceinline__ u64 f2u(float2 v) {
    u64 r; asm("mov.b64 %0, {%1, %2};" : "=l"(r) : "f"(v.x), "f"(v.y)); return r;
}
__device__ __forceinline__ unsigned h2u(__half2 h) { return *(unsigned*)&h; }
__device__ __forceinline__ float2 u2f2(unsigned u) { __half2 h = *(__half2*)&u; return __half22float2(h); }
__device__ __forceinline__ float sigmoid_(float v) { return 1.0f / (1.0f + __expf(-v)); }

// ---------------------------------------------------------------------------
// K1 v2 (unchanged — R6 verified): emb[b,c,i,t,j] = sum_d x[b,c,t,d,i]*pos[c,j,d]
// ---------------------------------------------------------------------------
__global__ void __launch_bounds__(256) k_emb2(const float* __restrict__ x,
                                              const float* __restrict__ pos)
{
    __shared__ float ps[32 * 36];
    __shared__ float xs[2][32 * 33];

    int bc = blockIdx.x;
    int c = bc % 3;
    int tid = threadIdx.x;

    {
        float4 pv = ((const float4*)(pos + c * 1024))[tid];
        int j = tid >> 3, d0 = (tid & 7) * 4;
        ps[(d0 + 0) * 36 + j] = pv.x;
        ps[(d0 + 1) * 36 + j] = pv.y;
        ps[(d0 + 2) * 36 + j] = pv.z;
        ps[(d0 + 3) * 36 + j] = pv.w;
    }

    const float* xb = x + (size_t)bc * 32768;
    float* ob = g_emb + (size_t)bc * 32768;
    int i  = tid >> 3, j0 = (tid & 7) * 4;
    int dd = tid >> 3, i4 = (tid & 7) * 4;

    for (int tg = 0; tg < 16; tg++) {
        float4 xv0 = ((const float4*)(xb + (size_t)(2 * tg)     * 1024))[tid];
        float4 xv1 = ((const float4*)(xb + (size_t)(2 * tg + 1) * 1024))[tid];
        __syncthreads();
        xs[0][dd * 33 + i4 + 0] = xv0.x; xs[0][dd * 33 + i4 + 1] = xv0.y;
        xs[0][dd * 33 + i4 + 2] = xv0.z; xs[0][dd * 33 + i4 + 3] = xv0.w;
        xs[1][dd * 33 + i4 + 0] = xv1.x; xs[1][dd * 33 + i4 + 1] = xv1.y;
        xs[1][dd * 33 + i4 + 2] = xv1.z; xs[1][dd * 33 + i4 + 3] = xv1.w;
        __syncthreads();

        u64 a00 = 0, a01 = 0, a10 = 0, a11 = 0;
#pragma unroll
        for (int d = 0; d < 32; d++) {
            ulonglong2 p = *(const ulonglong2*)(ps + d * 36 + j0);
            float x0 = xs[0][d * 33 + i];
            float x1 = xs[1][d * 33 + i];
            u64 x0p = pack2(x0, x0), x1p = pack2(x1, x1);
            a00 = fma2(x0p, p.x, a00); a01 = fma2(x0p, p.y, a01);
            a10 = fma2(x1p, p.x, a10); a11 = fma2(x1p, p.y, a11);
        }
        float b0, b1, b2, b3;
        unpack2(a00, b0, b1); unpack2(a01, b2, b3);
        *(float4*)(ob + (size_t)i * 1024 + (2 * tg) * 32 + j0) = make_float4(b0, b1, b2, b3);
        unpack2(a10, b0, b1); unpack2(a11, b2, b3);
        *(float4*)(ob + (size_t)i * 1024 + (2 * tg + 1) * 32 + j0) = make_float4(b0, b1, b2, b3);
    }
}

// ---------------------------------------------------------------------------
// K3 v3: y-branch, 2 tiles/warp, ALL global traffic coalesced and ALL
// per-lane smem at stride 33 (conflict-free). Weight/skv reads stay uniform.
// Per-warp smem: stA[1056] | stB[1056] | skv[256] = 2368 floats.
// ---------------------------------------------------------------------------
#define WY 4
__global__ void __launch_bounds__(WY * 32, 4) k_attn_y3(
    const float* __restrict__ Wqvk, const float* __restrict__ W0, int base)
{
    extern __shared__ float sm[];
    float* sW  = sm;          // 3072
    float* sW0 = sm + 3072;   // 1024

    int tid = threadIdx.x;
    int w = tid >> 5, lane = tid & 31;
    float* stA = sm + 4096 + w * 2368;
    float* stB = stA + 1056;
    float* skv = stB + 1056;  // 256

    int cid = base + blockIdx.x;
    int bc = cid >> 2;
    int ib = cid & 3;
    int c = bc % 3;

    for (int k = tid; k < 768; k += WY * 32) ((float4*)sW)[k]  = ((const float4*)(Wqvk + c * 3072))[k];
    for (int k = tid; k < 256; k += WY * 32) ((float4*)sW0)[k] = ((const float4*)(W0 + c * 1024))[k];
    __syncthreads();

    int i0 = ib * 8 + w * 2;
    const float* egA = g_emb + ((size_t)bc * 32 + i0) * 1024;
    const float* egB = egA + 1024;
    float* ogA = g_sig + ((size_t)bc * 32 + i0) * 1024;
    float* ogB = ogA + 1024;

    // ---- stage E coalesced -> stride-33 smem ----
#pragma unroll
    for (int r = 0; r < 32; r++) {
        stA[r * 33 + lane] = egA[r * 32 + lane];
        stB[r * 33 + lane] = egB[r * 32 + lane];
    }
    __syncwarp();

    // own rows -> packed regs (conflict-free scalar LDS)
    u64 e2A[16], e2B[16];
#pragma unroll
    for (int j = 0; j < 16; j++) {
        e2A[j] = pack2(stA[lane * 33 + 2 * j], stA[lane * 33 + 2 * j + 1]);
        e2B[j] = pack2(stB[lane * 33 + 2 * j], stB[lane * 33 + 2 * j + 1]);
    }
    __syncwarp();   // all lanes read E before stash overwrites

#pragma unroll 1
    for (int h = 0; h < 8; h++) {
        float qA[4], kA[4], vA[4], qB[4], kB[4], vB[4];
#pragma unroll
        for (int d = 0; d < 4; d++) {
            const ulonglong2* wq = (const ulonglong2*)(sW + (d * 24 + h)      * 32);
            const ulonglong2* wk = (const ulonglong2*)(sW + (d * 24 + 8 + h)  * 32);
            const ulonglong2* wv = (const ulonglong2*)(sW + (d * 24 + 16 + h) * 32);
            u64 aqA = 0, akA = 0, avA = 0, aqB = 0, akB = 0, avB = 0;
#pragma unroll
            for (int j = 0; j < 8; j++) {
                ulonglong2 ww;
                ww = wq[j];
                aqA = fma2(e2A[2*j+1], ww.y, fma2(e2A[2*j], ww.x, aqA));
                aqB = fma2(e2B[2*j+1], ww.y, fma2(e2B[2*j], ww.x, aqB));
                ww = wk[j];
                akA = fma2(e2A[2*j+1], ww.y, fma2(e2A[2*j], ww.x, akA));
                akB = fma2(e2B[2*j+1], ww.y, fma2(e2B[2*j], ww.x, akB));
                ww = wv[j];
                avA = fma2(e2A[2*j+1], ww.y, fma2(e2A[2*j], ww.x, avA));
                avB = fma2(e2B[2*j+1], ww.y, fma2(e2B[2*j], ww.x, avB));
            }
            float a, b;
            unpack2(aqA, a, b); qA[d] = (a + b) * 0.5f;   // fold DH^-0.5
            unpack2(akA, a, b); kA[d] = a + b;
            unpack2(avA, a, b); vA[d] = a + b;
            unpack2(aqB, a, b); qB[d] = (a + b) * 0.5f;
            unpack2(akB, a, b); kB[d] = a + b;
            unpack2(avB, a, b); vB[d] = a + b;
        }
        // fp16 K/V -> skv (dense across lanes: conflict-free)
        {
            uint4 uA, uB;
            uA.x = h2u(__floats2half2_rn(kA[0], kA[1]));
            uA.y = h2u(__floats2half2_rn(kA[2], kA[3]));
            uA.z = h2u(__floats2half2_rn(vA[0], vA[1]));
            uA.w = h2u(__floats2half2_rn(vA[2], vA[3]));
            uB.x = h2u(__floats2half2_rn(kB[0], kB[1]));
            uB.y = h2u(__floats2half2_rn(kB[2], kB[3]));
            uB.z = h2u(__floats2half2_rn(vB[0], vB[1]));
            uB.w = h2u(__floats2half2_rn(vB[2], vB[3]));
            *(uint4*)(skv + lane * 8)     = uA;
            *(uint4*)(skv + lane * 8 + 4) = uB;
        }
        u64 q01A = pack2(qA[0], qA[1]), q23A = pack2(qA[2], qA[3]);
        u64 q01B = pack2(qB[0], qB[1]), q23B = pack2(qB[2], qB[3]);
        __syncwarp();

        float sumA = 0.f, sumB = 0.f;
        u64 aA01 = 0, aA23 = 0, aB01 = 0, aB23 = 0;
#pragma unroll 8
        for (int s = 0; s < 32; s++) {
            uint4 uA = *(uint4*)(skv + s * 8);       // uniform: 1 wavefront
            uint4 uB = *(uint4*)(skv + s * 8 + 4);
            u64 tA = fma2(q23A, f2u(u2f2(uA.y)), mul2(q01A, f2u(u2f2(uA.x))));
            float ta, tb; unpack2(tA, ta, tb);
            float pA = __expf(ta + tb);
            sumA += pA;
            u64 p2A = pack2(pA, pA);
            aA01 = fma2(p2A, f2u(u2f2(uA.z)), aA01);
            aA23 = fma2(p2A, f2u(u2f2(uA.w)), aA23);
            u64 tB = fma2(q23B, f2u(u2f2(uB.y)), mul2(q01B, f2u(u2f2(uB.x))));
            unpack2(tB, ta, tb);
            float pB = __expf(ta + tb);
            sumB += pB;
            u64 p2B = pack2(pB, pB);
            aB01 = fma2(p2B, f2u(u2f2(uB.z)), aB01);
            aB23 = fma2(p2B, f2u(u2f2(uB.w)), aB23);
        }
        float invA = 1.f / sumA, invB = 1.f / sumB;
        float oa, ob, oc, od;
        // o stash: scalar stride-33 (banks lane+4h+k -> conflict-free)
        unpack2(aA01, oa, ob); unpack2(aA23, oc, od);
        stA[lane * 33 + 4*h + 0] = oa * invA; stA[lane * 33 + 4*h + 1] = ob * invA;
        stA[lane * 33 + 4*h + 2] = oc * invA; stA[lane * 33 + 4*h + 3] = od * invA;
        unpack2(aB01, oa, ob); unpack2(aB23, oc, od);
        stB[lane * 33 + 4*h + 0] = oa * invB; stB[lane * 33 + 4*h + 1] = ob * invB;
        stB[lane * 33 + 4*h + 2] = oc * invB; stB[lane * 33 + 4*h + 3] = od * invB;
        __syncwarp();
    }

    // ---- reload o rows (conflict-free scalar), W0 GEMV ----
    u64 o2A[16], o2B[16];
#pragma unroll
    for (int j = 0; j < 16; j++) {
        o2A[j] = pack2(stA[lane * 33 + 2 * j], stA[lane * 33 + 2 * j + 1]);
        o2B[j] = pack2(stB[lane * 33 + 2 * j], stB[lane * 33 + 2 * j + 1]);
    }
    __syncwarp();   // all reloaded before proj staging overwrites

#pragma unroll
    for (int j = 0; j < 32; j++) {
        const ulonglong2* wr = (const ulonglong2*)(sW0 + j * 32);  // uniform
        u64 accA = 0, accB = 0;
#pragma unroll
        for (int m = 0; m < 8; m++) {
            ulonglong2 ww = wr[m];
            accA = fma2(o2A[2*m+1], ww.y, fma2(o2A[2*m], ww.x, accA));
            accB = fma2(o2B[2*m+1], ww.y, fma2(o2B[2*m], ww.x, accB));
        }
        float xa, xb;
        unpack2(accA, xa, xb); stA[lane * 33 + j] = xa + xb;   // conflict-free
        unpack2(accB, xa, xb); stB[lane * 33 + j] = xa + xb;
    }
    __syncwarp();

    // ---- coalesced stores ----
#pragma unroll
    for (int r = 0; r < 32; r++) {
        ogA[r * 32 + lane] = stA[r * 33 + lane];
        ogB[r * 32 + lane] = stB[r * 33 + lane];
    }
}

// ---------------------------------------------------------------------------
// x-branch full warp attention (unchanged)
// ---------------------------------------------------------------------------
__device__ __forceinline__ void warp_attn_full(
    int lane,
    const float* __restrict__ eg, float* __restrict__ og,
    const float* __restrict__ sW, const float* __restrict__ sW0,
    const float* __restrict__ sgb, float* __restrict__ skv)
{
    u64 e2[16];
    {
        const ulonglong2* ep = (const ulonglong2*)(eg + lane * 32);
#pragma unroll
        for (int j = 0; j < 8; j++) { ulonglong2 v = ep[j]; e2[2*j] = v.x; e2[2*j+1] = v.y; }
    }
    float rr[32];
#pragma unroll
    for (int j = 0; j < 16; j++) unpack2(e2[j], rr[2*j], rr[2*j+1]);

#pragma unroll 1
    for (int h = 0; h < 8; h++) {
        float q[4], kk[4], vv[4];
#pragma unroll
        for (int d = 0; d < 4; d++) {
            const ulonglong2* wq = (const ulonglong2*)(sW + (d * 24 + h)      * 32);
            const ulonglong2* wk = (const ulonglong2*)(sW + (d * 24 + 8 + h)  * 32);
            const ulonglong2* wv = (const ulonglong2*)(sW + (d * 24 + 16 + h) * 32);
            u64 aq = 0, ak = 0, av = 0;
#pragma unroll
            for (int j = 0; j < 8; j++) {
                ulonglong2 ww;
                ww = wq[j]; aq = fma2(e2[2*j+1], ww.y, fma2(e2[2*j], ww.x, aq));
                ww = wk[j]; ak = fma2(e2[2*j+1], ww.y, fma2(e2[2*j], ww.x, ak));
                ww = wv[j]; av = fma2(e2[2*j+1], ww.y, fma2(e2[2*j], ww.x, av));
            }
            float a, b;
            unpack2(aq, a, b); q[d]  = (a + b) * 0.5f;
            unpack2(ak, a, b); kk[d] = a + b;
            unpack2(av, a, b); vv[d] = a + b;
        }
        *(float4*)(skv + lane * 12)     = make_float4(kk[0], kk[1], kk[2], kk[3]);
        *(float4*)(skv + lane * 12 + 4) = make_float4(vv[0], vv[1], vv[2], vv[3]);
        u64 q01 = pack2(q[0], q[1]), q23 = pack2(q[2], q[3]);
        __syncwarp();

        float sum = 0.f;
        u64 a01 = 0, a23 = 0;
#pragma unroll
        for (int s = 0; s < 32; s++) {
            ulonglong2 k2 = *(const ulonglong2*)(skv + s * 12);
            ulonglong2 v2 = *(const ulonglong2*)(skv + s * 12 + 4);
            u64 t = fma2(q23, k2.y, mul2(q01, k2.x));
            float ta, tb; unpack2(t, ta, tb);
            float p = __expf(ta + tb);
            sum += p;
            u64 p2 = pack2(p, p);
            a01 = fma2(p2, v2.x, a01);
            a23 = fma2(p2, v2.y, a23);
        }
        __syncwarp();
        float inv = 1.f / sum;
        float oa, ob, oc, od;
        unpack2(a01, oa, ob); unpack2(a23, oc, od);
        u64 o01 = pack2(oa * inv, ob * inv), o23 = pack2(oc * inv, od * inv);

        const float* w0h = sW0 + 4 * h;
#pragma unroll
        for (int j = 0; j < 32; j += 2) {
            ulonglong2 wa = *(const ulonglong2*)(w0h + j * 32);
            ulonglong2 wb = *(const ulonglong2*)(w0h + (j + 1) * 32);
            u64 ra = fma2(o23, wa.y, mul2(o01, wa.x));
            u64 rb = fma2(o23, wb.y, mul2(o01, wb.x));
            float xa, xb;
            unpack2(ra, xa, xb); rr[j]     += xa + xb;
            unpack2(rb, xa, xb); rr[j + 1] += xa + xb;
        }
    }

    float s1 = 0.f;
#pragma unroll
    for (int j = 0; j < 32; j++) s1 += rr[j];
    float mu = s1 * 0.03125f;
    float sq = 0.f;
#pragma unroll
    for (int j = 0; j < 32; j++) { float d = rr[j] - mu; sq = fmaf(d, d, sq); }
    float rstd = rsqrtf(sq * 0.03125f + 1e-5f);

    float* po = og + lane * 32;
#pragma unroll
    for (int j = 0; j < 32; j += 4) {
        float4 v;
        v.x = sigmoid_((rr[j]     - mu) * rstd * sgb[j]     + sgb[32 + j]);
        v.y = sigmoid_((rr[j + 1] - mu) * rstd * sgb[j + 1] + sgb[33 + j]);
        v.z = sigmoid_((rr[j + 2] - mu) * rstd * sgb[j + 2] + sgb[34 + j]);
        v.w = sigmoid_((rr[j + 3] - mu) * rstd * sgb[j + 3] + sgb[35 + j]);
        *(float4*)(po + j) = v;
    }
}

__global__ void __launch_bounds__(128) k_attn_x2(
    const float* __restrict__ Wqvk, const float* __restrict__ W0,
    const float* __restrict__ g, const float* __restrict__ b, int nb4)
{
    __shared__ float sW[3072];
    __shared__ float sW0[1024];
    __shared__ float sgb[64];
    __shared__ float tiles[4 * 384];

    int tid = threadIdx.x;
    int w = tid >> 5, lane = tid & 31;
    int c  = blockIdx.x / nb4;
    int bq = blockIdx.x % nb4;

    for (int k = tid; k < 768; k += 128) ((float4*)sW)[k]  = ((const float4*)(Wqvk + c * 3072))[k];
    for (int k = tid; k < 256; k += 128) ((float4*)sW0)[k] = ((const float4*)(W0 + c * 1024))[k];
    if (tid < 32) { sgb[tid] = g[tid]; sgb[32 + tid] = b[tid]; }
    __syncthreads();

    int bb = bq * 4 + w;
    const float* eg = g_emb + (((size_t)bb * 3 + 2) * 32 + 31) * 1024;
    float* og = g_sg2 + ((size_t)bb * 3 + c) * 1024;
    warp_attn_full(lane, eg, og, sW, sW0, sgb, tiles + w * 384);
}

// ---------------------------------------------------------------------------
// K4 (unchanged): gate_y = sigmoid(LN(emb + proj)); out = sg2 * gate_y * x.
// ---------------------------------------------------------------------------
__global__ void __launch_bounds__(256) k_final(const float* __restrict__ x,
                                               const float* __restrict__ gam,
                                               const float* __restrict__ bet,
                                               float* __restrict__ out)
{
    __shared__ float gs[32 * 33];
    __shared__ float ss[32];
    int bct = blockIdx.x;
    int t = bct & 31;
    int bc = bct >> 5;
    int tid = threadIdx.x;

    int i = tid >> 3, j0 = (tid & 7) * 4;
    size_t base = ((size_t)bc * 32 + i) * 1024 + t * 32 + j0;
    float4 pv = *(const float4*)(g_sig + base);
    float4 ev = *(const float4*)(g_emb + base);
    float4 v;
    v.x = pv.x + ev.x; v.y = pv.y + ev.y; v.z = pv.z + ev.z; v.w = pv.w + ev.w;

    float s1 = v.x + v.y + v.z + v.w;
    float s2 = fmaf(v.x, v.x, fmaf(v.y, v.y, fmaf(v.z, v.z, v.w * v.w)));
#pragma unroll
    for (int m = 1; m < 8; m <<= 1) {
        s1 += __shfl_xor_sync(0xffffffffu, s1, m);
        s2 += __shfl_xor_sync(0xffffffffu, s2, m);
    }
    float mu = s1 * 0.03125f;
    float var = fmaf(-mu, mu, s2 * 0.03125f);
    float rstd = rsqrtf(var + 1e-5f);

    float4 gm = *(const float4*)(gam + j0);
    float4 bt = *(const float4*)(bet + j0);
    gs[i * 33 + j0 + 0] = sigmoid_((v.x - mu) * rstd * gm.x + bt.x);
    gs[i * 33 + j0 + 1] = sigmoid_((v.y - mu) * rstd * gm.y + bt.y);
    gs[i * 33 + j0 + 2] = sigmoid_((v.z - mu) * rstd * gm.z + bt.z);
    gs[i * 33 + j0 + 3] = sigmoid_((v.w - mu) * rstd * gm.w + bt.w);
    if (tid < 32) ss[tid] = g_sg2[(size_t)bc * 1024 + tid * 32 + t];
    __syncthreads();

    float4 xv = ((const float4*)(x + (size_t)bct * 1024))[tid];
    int jj = tid >> 3, i0 = (tid & 7) * 4;
    float4 ov;
    ov.x = ss[i0 + 0] * gs[(i0 + 0) * 33 + jj] * xv.x;
    ov.y = ss[i0 + 1] * gs[(i0 + 1) * 33 + jj] * xv.y;
    ov.z = ss[i0 + 2] * gs[(i0 + 2) * 33 + jj] * xv.z;
    ov.w = ss[i0 + 3] * gs[(i0 + 3) * 33 + jj] * xv.w;
    ((float4*)(out + (size_t)bct * 1024))[tid] = ov;
}

// ---------------------------------------------------------------------------
extern "C" void kernel_launch(void* const* d_in, const int* in_sizes, int n_in,
                              void* d_out, int out_size)
{
    const float* x   = (const float*)d_in[0];
    const float* pos = (const float*)d_in[1];
    const float* Wqy = (const float*)d_in[2];
    const float* W0y = (const float*)d_in[3];
    const float* gy  = (const float*)d_in[4];
    const float* by  = (const float*)d_in[5];
    const float* Wqx = (const float*)d_in[6];
    const float* W0x = (const float*)d_in[7];
    const float* gx  = (const float*)d_in[8];
    const float* bx  = (const float*)d_in[9];
    float* out = (float*)d_out;

    int B = in_sizes[0] / 98304;  // 3*32*32*32

    const int SMEM_Y = (4096 + WY * 2368) * 4;   // 54,272 B
    cudaFuncSetAttribute(k_attn_y3, cudaFuncAttributeMaxDynamicSharedMemorySize, SMEM_Y);

    int nY = B * 12;
    int h1 = nY / 2;
    int nb4 = B / 4;

    k_emb2<<<B * 3, 256>>>(x, pos);
    k_attn_x2<<<3 * nb4, 128>>>(Wqx, W0x, gx, bx, nb4);
    k_attn_y3<<<h1, WY * 32, SMEM_Y>>>(Wqy, W0y, 0);
    k_attn_y3<<<nY - h1, WY * 32, SMEM_Y>>>(Wqy, W0y, h1);
    k_final<<<B * 96, 256>>>(x, gy, by, out);
}

// round 8
// speedup vs baseline: 1.8634x; 1.0357x over previous
#include <cuda_runtime.h>
#include <cuda_fp16.h>

typedef unsigned long long u64;

#define B_MAX 256

__device__ float g_emb[B_MAX * 3 * 32 * 32 * 32];  // [b][c][i][t][j]
__device__ float g_sig[B_MAX * 3 * 32 * 32 * 32];  // y-branch residual (emb + proj)
__device__ float g_sg2[B_MAX * 3 * 32 * 32];       // sigmoid(LN(x-branch))

// ---------------- packed f32x2 helpers ----------------
__device__ __forceinline__ u64 pack2(float lo, float hi) {
    u64 r; asm("mov.b64 %0, {%1, %2};" : "=l"(r) : "f"(lo), "f"(hi)); return r;
}
__device__ __forceinline__ void unpack2(u64 v, float& lo, float& hi) {
    asm("mov.b64 {%0, %1}, %2;" : "=f"(lo), "=f"(hi) : "l"(v));
}
__device__ __forceinline__ u64 fma2(u64 a, u64 b, u64 c) {
    u64 d; asm("fma.rn.f32x2 %0, %1, %2, %3;" : "=l"(d) : "l"(a), "l"(b), "l"(c)); return d;
}
__device__ __forceinline__ u64 mul2(u64 a, u64 b) {
    u64 d; asm("mul.rn.f32x2 %0, %1, %2;" : "=l"(d) : "l"(a), "l"(b)); return d;
}
__device__ __forceinline__ u64 f2u(float2 v) {
    u64 r; asm("mov.b64 %0, {%1, %2};" : "=l"(r) : "f"(v.x), "f"(v.y)); return r;
}
__device__ __forceinline__ unsigned h2u(__half2 h) { return *(unsigned*)&h; }
__device__ __forceinline__ float2 u2f2(unsigned u) { __half2 h = *(__half2*)&u; return __half22float2(h); }
__device__ __forceinline__ float ex2_(float x) {
    float r; asm("ex2.approx.f32 %0, %1;" : "=f"(r) : "f"(x)); return r;
}
__device__ __forceinline__ float sigmoid_(float v) { return 1.0f / (1.0f + __expf(-v)); }

// ---------------------------------------------------------------------------
// K1 v2 (unchanged): emb[b,c,i,t,j] = sum_d x[b,c,t,d,i]*pos[c,j,d]
// ---------------------------------------------------------------------------
__global__ void __launch_bounds__(256) k_emb2(const float* __restrict__ x,
                                              const float* __restrict__ pos)
{
    __shared__ float ps[32 * 36];
    __shared__ float xs[2][32 * 33];

    int bc = blockIdx.x;
    int c = bc % 3;
    int tid = threadIdx.x;

    {
        float4 pv = ((const float4*)(pos + c * 1024))[tid];
        int j = tid >> 3, d0 = (tid & 7) * 4;
        ps[(d0 + 0) * 36 + j] = pv.x;
        ps[(d0 + 1) * 36 + j] = pv.y;
        ps[(d0 + 2) * 36 + j] = pv.z;
        ps[(d0 + 3) * 36 + j] = pv.w;
    }

    const float* xb = x + (size_t)bc * 32768;
    float* ob = g_emb + (size_t)bc * 32768;
    int i  = tid >> 3, j0 = (tid & 7) * 4;
    int dd = tid >> 3, i4 = (tid & 7) * 4;

    for (int tg = 0; tg < 16; tg++) {
        float4 xv0 = ((const float4*)(xb + (size_t)(2 * tg)     * 1024))[tid];
        float4 xv1 = ((const float4*)(xb + (size_t)(2 * tg + 1) * 1024))[tid];
        __syncthreads();
        xs[0][dd * 33 + i4 + 0] = xv0.x; xs[0][dd * 33 + i4 + 1] = xv0.y;
        xs[0][dd * 33 + i4 + 2] = xv0.z; xs[0][dd * 33 + i4 + 3] = xv0.w;
        xs[1][dd * 33 + i4 + 0] = xv1.x; xs[1][dd * 33 + i4 + 1] = xv1.y;
        xs[1][dd * 33 + i4 + 2] = xv1.z; xs[1][dd * 33 + i4 + 3] = xv1.w;
        __syncthreads();

        u64 a00 = 0, a01 = 0, a10 = 0, a11 = 0;
#pragma unroll
        for (int d = 0; d < 32; d++) {
            ulonglong2 p = *(const ulonglong2*)(ps + d * 36 + j0);
            float x0 = xs[0][d * 33 + i];
            float x1 = xs[1][d * 33 + i];
            u64 x0p = pack2(x0, x0), x1p = pack2(x1, x1);
            a00 = fma2(x0p, p.x, a00); a01 = fma2(x0p, p.y, a01);
            a10 = fma2(x1p, p.x, a10); a11 = fma2(x1p, p.y, a11);
        }
        float b0, b1, b2, b3;
        unpack2(a00, b0, b1); unpack2(a01, b2, b3);
        *(float4*)(ob + (size_t)i * 1024 + (2 * tg) * 32 + j0) = make_float4(b0, b1, b2, b3);
        unpack2(a10, b0, b1); unpack2(a11, b2, b3);
        *(float4*)(ob + (size_t)i * 1024 + (2 * tg + 1) * 32 + j0) = make_float4(b0, b1, b2, b3);
    }
}

// ---------------------------------------------------------------------------
// K3 v5: y-branch. ONE tile per warp, 6 CTAs/SM target.
// Per-warp smem: st[1056] (E-stage -> o-stash -> out-stage) + skv[128] (fp16 KV).
// Writes RESIDUAL (E + proj); LN+sigmoid in k_final.
// ---------------------------------------------------------------------------
__global__ void __launch_bounds__(128, 6) k_attn_y5(
    const float* __restrict__ Wqvk, const float* __restrict__ W0, int base)
{
    __shared__ float sW[3072];
    __shared__ float sW0[1024];
    __shared__ float stb[4 * 1184];   // per warp: st 1056 | skv 128

    int tid = threadIdx.x;
    int w = tid >> 5, lane = tid & 31;
    float* st  = stb + w * 1184;
    float* skv = st + 1056;

    int cid = base + blockIdx.x;
    int bc = cid >> 3;       // b*3 + c
    int ib = cid & 7;        // 8 CTAs per bc, 4 tiles each
    int c = bc % 3;

    for (int k = tid; k < 768; k += 128) ((float4*)sW)[k]  = ((const float4*)(Wqvk + c * 3072))[k];
    for (int k = tid; k < 256; k += 128) ((float4*)sW0)[k] = ((const float4*)(W0 + c * 1024))[k];
    __syncthreads();

    int i = ib * 4 + w;
    const float* eg = g_emb + ((size_t)bc * 32 + i) * 1024;
    float* og       = g_sig + ((size_t)bc * 32 + i) * 1024;

    // ---- stage E coalesced -> stride-33, then own row -> regs ----
#pragma unroll
    for (int r = 0; r < 32; r++) st[r * 33 + lane] = eg[r * 32 + lane];
    __syncwarp();

    u64 e2[16];
#pragma unroll
    for (int j = 0; j < 16; j++)
        e2[j] = pack2(st[lane * 33 + 2 * j], st[lane * 33 + 2 * j + 1]);
    // (o-stash below writes only this lane's own row — no cross-lane hazard)

    const float QS = 0.72134752044f;   // 0.5 * log2(e)  (DH^-0.5 and exp2 folded)

#pragma unroll 1
    for (int h = 0; h < 8; h++) {
        float q[4], kk[4], vv[4];
#pragma unroll
        for (int d = 0; d < 4; d++) {
            const ulonglong2* wq = (const ulonglong2*)(sW + (d * 24 + h)      * 32);
            const ulonglong2* wk = (const ulonglong2*)(sW + (d * 24 + 8 + h)  * 32);
            const ulonglong2* wv = (const ulonglong2*)(sW + (d * 24 + 16 + h) * 32);
            u64 aq = 0, ak = 0, av = 0;
#pragma unroll
            for (int j = 0; j < 8; j++) {
                ulonglong2 ww;
                ww = wq[j]; aq = fma2(e2[2*j+1], ww.y, fma2(e2[2*j], ww.x, aq));
                ww = wk[j]; ak = fma2(e2[2*j+1], ww.y, fma2(e2[2*j], ww.x, ak));
                ww = wv[j]; av = fma2(e2[2*j+1], ww.y, fma2(e2[2*j], ww.x, av));
            }
            float a, b;
            unpack2(aq, a, b); q[d]  = (a + b) * QS;
            unpack2(ak, a, b); kk[d] = a + b;
            unpack2(av, a, b); vv[d] = a + b;
        }
        // fp16 K/V -> skv (16B/lane, dense: conflict-free)
        {
            uint4 u;
            u.x = h2u(__floats2half2_rn(kk[0], kk[1]));
            u.y = h2u(__floats2half2_rn(kk[2], kk[3]));
            u.z = h2u(__floats2half2_rn(vv[0], vv[1]));
            u.w = h2u(__floats2half2_rn(vv[2], vv[3]));
            *(uint4*)(skv + lane * 4) = u;
        }
        u64 q01 = pack2(q[0], q[1]), q23 = pack2(q[2], q[3]);
        __syncwarp();

        // ---- fused softmax(exp2) + AV ----
        float sum = 0.f;
        u64 a01 = 0, a23 = 0;
#pragma unroll 8
        for (int s = 0; s < 32; s++) {
            uint4 u = *(uint4*)(skv + s * 4);   // uniform broadcast
            u64 t = fma2(q23, f2u(u2f2(u.y)), mul2(q01, f2u(u2f2(u.x))));
            float ta, tb; unpack2(t, ta, tb);
            float p = ex2_(ta + tb);
            sum += p;
            u64 p2 = pack2(p, p);
            a01 = fma2(p2, f2u(u2f2(u.z)), a01);
            a23 = fma2(p2, f2u(u2f2(u.w)), a23);
        }
        float inv = 1.f / sum;
        float oa, ob, oc, od;
        unpack2(a01, oa, ob); unpack2(a23, oc, od);
        // o-stash: own row, stride-33 scalar (conflict-free)
        st[lane * 33 + 4*h + 0] = oa * inv;
        st[lane * 33 + 4*h + 1] = ob * inv;
        st[lane * 33 + 4*h + 2] = oc * inv;
        st[lane * 33 + 4*h + 3] = od * inv;
        __syncwarp();   // all lanes done reading skv before next head overwrites
    }

    // ---- reload o (own row), W0 GEMV + residual, stage transposed ----
    u64 o2[16];
#pragma unroll
    for (int j = 0; j < 16; j++)
        o2[j] = pack2(st[lane * 33 + 2 * j], st[lane * 33 + 2 * j + 1]);

#pragma unroll
    for (int j = 0; j < 32; j += 2) {
        const ulonglong2* wr = (const ulonglong2*)(sW0 + j * 32);
        const ulonglong2* ws = (const ulonglong2*)(sW0 + (j + 1) * 32);
        u64 acc = 0, acd = 0;
#pragma unroll
        for (int m = 0; m < 8; m++) {
            acc = fma2(o2[2*m+1], wr[m].y, fma2(o2[2*m], wr[m].x, acc));
            acd = fma2(o2[2*m+1], ws[m].y, fma2(o2[2*m], ws[m].x, acd));
        }
        float xa, xb, ea, eb;
        unpack2(e2[j >> 1], ea, eb);
        unpack2(acc, xa, xb); st[lane * 33 + j]     = xa + xb + ea;
        unpack2(acd, xa, xb); st[lane * 33 + j + 1] = xa + xb + eb;
    }
    __syncwarp();

    // ---- coalesced store of residual ----
#pragma unroll
    for (int r = 0; r < 32; r++) og[r * 32 + lane] = st[r * 33 + lane];
}

// ---------------------------------------------------------------------------
// x-branch full warp attention (unchanged)
// ---------------------------------------------------------------------------
__device__ __forceinline__ void warp_attn_full(
    int lane,
    const float* __restrict__ eg, float* __restrict__ og,
    const float* __restrict__ sW, const float* __restrict__ sW0,
    const float* __restrict__ sgb, float* __restrict__ skv)
{
    u64 e2[16];
    {
        const ulonglong2* ep = (const ulonglong2*)(eg + lane * 32);
#pragma unroll
        for (int j = 0; j < 8; j++) { ulonglong2 v = ep[j]; e2[2*j] = v.x; e2[2*j+1] = v.y; }
    }
    float rr[32];
#pragma unroll
    for (int j = 0; j < 16; j++) unpack2(e2[j], rr[2*j], rr[2*j+1]);

#pragma unroll 1
    for (int h = 0; h < 8; h++) {
        float q[4], kk[4], vv[4];
#pragma unroll
        for (int d = 0; d < 4; d++) {
            const ulonglong2* wq = (const ulonglong2*)(sW + (d * 24 + h)      * 32);
            const ulonglong2* wk = (const ulonglong2*)(sW + (d * 24 + 8 + h)  * 32);
            const ulonglong2* wv = (const ulonglong2*)(sW + (d * 24 + 16 + h) * 32);
            u64 aq = 0, ak = 0, av = 0;
#pragma unroll
            for (int j = 0; j < 8; j++) {
                ulonglong2 ww;
                ww = wq[j]; aq = fma2(e2[2*j+1], ww.y, fma2(e2[2*j], ww.x, aq));
                ww = wk[j]; ak = fma2(e2[2*j+1], ww.y, fma2(e2[2*j], ww.x, ak));
                ww = wv[j]; av = fma2(e2[2*j+1], ww.y, fma2(e2[2*j], ww.x, av));
            }
            float a, b;
            unpack2(aq, a, b); q[d]  = (a + b) * 0.5f;
            unpack2(ak, a, b); kk[d] = a + b;
            unpack2(av, a, b); vv[d] = a + b;
        }
        *(float4*)(skv + lane * 12)     = make_float4(kk[0], kk[1], kk[2], kk[3]);
        *(float4*)(skv + lane * 12 + 4) = make_float4(vv[0], vv[1], vv[2], vv[3]);
        u64 q01 = pack2(q[0], q[1]), q23 = pack2(q[2], q[3]);
        __syncwarp();

        float sum = 0.f;
        u64 a01 = 0, a23 = 0;
#pragma unroll
        for (int s = 0; s < 32; s++) {
            ulonglong2 k2 = *(const ulonglong2*)(skv + s * 12);
            ulonglong2 v2 = *(const ulonglong2*)(skv + s * 12 + 4);
            u64 t = fma2(q23, k2.y, mul2(q01, k2.x));
            float ta, tb; unpack2(t, ta, tb);
            float p = __expf(ta + tb);
            sum += p;
            u64 p2 = pack2(p, p);
            a01 = fma2(p2, v2.x, a01);
            a23 = fma2(p2, v2.y, a23);
        }
        __syncwarp();
        float inv = 1.f / sum;
        float oa, ob, oc, od;
        unpack2(a01, oa, ob); unpack2(a23, oc, od);
        u64 o01 = pack2(oa * inv, ob * inv), o23 = pack2(oc * inv, od * inv);

        const float* w0h = sW0 + 4 * h;
#pragma unroll
        for (int j = 0; j < 32; j += 2) {
            ulonglong2 wa = *(const ulonglong2*)(w0h + j * 32);
            ulonglong2 wb = *(const ulonglong2*)(w0h + (j + 1) * 32);
            u64 ra = fma2(o23, wa.y, mul2(o01, wa.x));
            u64 rb = fma2(o23, wb.y, mul2(o01, wb.x));
            float xa, xb;
            unpack2(ra, xa, xb); rr[j]     += xa + xb;
            unpack2(rb, xa, xb); rr[j + 1] += xa + xb;
        }
    }

    float s1 = 0.f;
#pragma unroll
    for (int j = 0; j < 32; j++) s1 += rr[j];
    float mu = s1 * 0.03125f;
    float sq = 0.f;
#pragma unroll
    for (int j = 0; j < 32; j++) { float d = rr[j] - mu; sq = fmaf(d, d, sq); }
    float rstd = rsqrtf(sq * 0.03125f + 1e-5f);

    float* po = og + lane * 32;
#pragma unroll
    for (int j = 0; j < 32; j += 4) {
        float4 v;
        v.x = sigmoid_((rr[j]     - mu) * rstd * sgb[j]     + sgb[32 + j]);
        v.y = sigmoid_((rr[j + 1] - mu) * rstd * sgb[j + 1] + sgb[33 + j]);
        v.z = sigmoid_((rr[j + 2] - mu) * rstd * sgb[j + 2] + sgb[34 + j]);
        v.w = sigmoid_((rr[j + 3] - mu) * rstd * sgb[j + 3] + sgb[35 + j]);
        *(float4*)(po + j) = v;
    }
}

__global__ void __launch_bounds__(128) k_attn_x2(
    const float* __restrict__ Wqvk, const float* __restrict__ W0,
    const float* __restrict__ g, const float* __restrict__ b, int nb4)
{
    __shared__ float sW[3072];
    __shared__ float sW0[1024];
    __shared__ float sgb[64];
    __shared__ float tiles[4 * 384];

    int tid = threadIdx.x;
    int w = tid >> 5, lane = tid & 31;
    int c  = blockIdx.x / nb4;
    int bq = blockIdx.x % nb4;

    for (int k = tid; k < 768; k += 128) ((float4*)sW)[k]  = ((const float4*)(Wqvk + c * 3072))[k];
    for (int k = tid; k < 256; k += 128) ((float4*)sW0)[k] = ((const float4*)(W0 + c * 1024))[k];
    if (tid < 32) { sgb[tid] = g[tid]; sgb[32 + tid] = b[tid]; }
    __syncthreads();

    int bb = bq * 4 + w;
    const float* eg = g_emb + (((size_t)bb * 3 + 2) * 32 + 31) * 1024;
    float* og = g_sg2 + ((size_t)bb * 3 + c) * 1024;
    warp_attn_full(lane, eg, og, sW, sW0, sgb, tiles + w * 384);
}

// ---------------------------------------------------------------------------
// K4 v2: g_sig now holds residual. gate_y = sigmoid(LN(res)); out = sg2*gate*x.
// ---------------------------------------------------------------------------
__global__ void __launch_bounds__(256) k_final(const float* __restrict__ x,
                                               const float* __restrict__ gam,
                                               const float* __restrict__ bet,
                                               float* __restrict__ out)
{
    __shared__ float gs[32 * 33];
    __shared__ float ss[32];
    int bct = blockIdx.x;
    int t = bct & 31;
    int bc = bct >> 5;
    int tid = threadIdx.x;

    int i = tid >> 3, j0 = (tid & 7) * 4;
    size_t base = ((size_t)bc * 32 + i) * 1024 + t * 32 + j0;
    float4 v = *(const float4*)(g_sig + base);

    float s1 = v.x + v.y + v.z + v.w;
    float s2 = fmaf(v.x, v.x, fmaf(v.y, v.y, fmaf(v.z, v.z, v.w * v.w)));
#pragma unroll
    for (int m = 1; m < 8; m <<= 1) {
        s1 += __shfl_xor_sync(0xffffffffu, s1, m);
        s2 += __shfl_xor_sync(0xffffffffu, s2, m);
    }
    float mu = s1 * 0.03125f;
    float var = fmaf(-mu, mu, s2 * 0.03125f);
    float rstd = rsqrtf(var + 1e-5f);

    float4 gm = *(const float4*)(gam + j0);
    float4 bt = *(const float4*)(bet + j0);
    gs[i * 33 + j0 + 0] = sigmoid_((v.x - mu) * rstd * gm.x + bt.x);
    gs[i * 33 + j0 + 1] = sigmoid_((v.y - mu) * rstd * gm.y + bt.y);
    gs[i * 33 + j0 + 2] = sigmoid_((v.z - mu) * rstd * gm.z + bt.z);
    gs[i * 33 + j0 + 3] = sigmoid_((v.w - mu) * rstd * gm.w + bt.w);
    if (tid < 32) ss[tid] = g_sg2[(size_t)bc * 1024 + tid * 32 + t];
    __syncthreads();

    float4 xv = ((const float4*)(x + (size_t)bct * 1024))[tid];
    int jj = tid >> 3, i0 = (tid & 7) * 4;
    float4 ov;
    ov.x = ss[i0 + 0] * gs[(i0 + 0) * 33 + jj] * xv.x;
    ov.y = ss[i0 + 1] * gs[(i0 + 1) * 33 + jj] * xv.y;
    ov.z = ss[i0 + 2] * gs[(i0 + 2) * 33 + jj] * xv.z;
    ov.w = ss[i0 + 3] * gs[(i0 + 3) * 33 + jj] * xv.w;
    ((float4*)(out + (size_t)bct * 1024))[tid] = ov;
}

// ---------------------------------------------------------------------------
extern "C" void kernel_launch(void* const* d_in, const int* in_sizes, int n_in,
                              void* d_out, int out_size)
{
    const float* x   = (const float*)d_in[0];
    const float* pos = (const float*)d_in[1];
    const float* Wqy = (const float*)d_in[2];
    const float* W0y = (const float*)d_in[3];
    const float* gy  = (const float*)d_in[4];
    const float* by  = (const float*)d_in[5];
    const float* Wqx = (const float*)d_in[6];
    const float* W0x = (const float*)d_in[7];
    const float* gx  = (const float*)d_in[8];
    const float* bx  = (const float*)d_in[9];
    float* out = (float*)d_out;

    int B = in_sizes[0] / 98304;  // 3*32*32*32

    int nY = B * 24;          // 6144 CTAs (4 tiles each)
    int h1 = nY / 2;
    int nb4 = B / 4;

    k_emb2<<<B * 3, 256>>>(x, pos);
    k_attn_x2<<<3 * nb4, 128>>>(Wqx, W0x, gx, bx, nb4);
    k_attn_y5<<<h1, 128>>>(Wqy, W0y, 0);
    k_attn_y5<<<nY - h1, 128>>>(Wqy, W0y, h1);
    k_final<<<B * 96, 256>>>(x, gy, by, out);
}

// round 9
// speedup vs baseline: 2.0422x; 1.0960x over previous
#include <cuda_runtime.h>
#include <cuda_fp16.h>

typedef unsigned long long u64;

#define B_MAX 256

__device__ float g_emb[B_MAX * 3 * 32 * 32 * 32];  // [b][c][i][t][j]
__device__ float g_sig[B_MAX * 3 * 32 * 32 * 32];  // y-branch residual (emb + proj)
__device__ float g_sg2[B_MAX * 3 * 32 * 32];       // sigmoid(LN(x-branch))

// ---------------- packed f32x2 + misc helpers ----------------
__device__ __forceinline__ u64 pack2(float lo, float hi) {
    u64 r; asm("mov.b64 %0, {%1, %2};" : "=l"(r) : "f"(lo), "f"(hi)); return r;
}
__device__ __forceinline__ void unpack2(u64 v, float& lo, float& hi) {
    asm("mov.b64 {%0, %1}, %2;" : "=f"(lo), "=f"(hi) : "l"(v));
}
__device__ __forceinline__ u64 fma2(u64 a, u64 b, u64 c) {
    u64 d; asm("fma.rn.f32x2 %0, %1, %2, %3;" : "=l"(d) : "l"(a), "l"(b), "l"(c)); return d;
}
__device__ __forceinline__ u64 mul2(u64 a, u64 b) {
    u64 d; asm("mul.rn.f32x2 %0, %1, %2;" : "=l"(d) : "l"(a), "l"(b)); return d;
}
__device__ __forceinline__ u64 f2u(float2 v) {
    u64 r; asm("mov.b64 %0, {%1, %2};" : "=l"(r) : "f"(v.x), "f"(v.y)); return r;
}
__device__ __forceinline__ unsigned h2u(__half2 h) { return *(unsigned*)&h; }
__device__ __forceinline__ float2 u2f2(unsigned u) { __half2 h = *(__half2*)&u; return __half22float2(h); }
__device__ __forceinline__ float ex2_(float x) {
    float r; asm("ex2.approx.f32 %0, %1;" : "=f"(r) : "f"(x)); return r;
}
__device__ __forceinline__ float sigmoid_(float v) { return 1.0f / (1.0f + __expf(-v)); }
__device__ __forceinline__ unsigned tf32_(float x) {
    unsigned u; asm("cvt.rna.tf32.f32 %0, %1;" : "=r"(u) : "f"(x)); return u;
}
__device__ __forceinline__ void mma_(float c[4], const unsigned a[4], const unsigned b[2]) {
    asm volatile(
        "mma.sync.aligned.m16n8k8.row.col.f32.tf32.tf32.f32 "
        "{%0,%1,%2,%3}, {%4,%5,%6,%7}, {%8,%9}, {%0,%1,%2,%3};"
        : "+f"(c[0]), "+f"(c[1]), "+f"(c[2]), "+f"(c[3])
        : "r"(a[0]), "r"(a[1]), "r"(a[2]), "r"(a[3]), "r"(b[0]), "r"(b[1]));
}

// ---------------------------------------------------------------------------
// K1 v2 (unchanged, verified): emb[b,c,i,t,j] = sum_d x[b,c,t,d,i]*pos[c,j,d]
// ---------------------------------------------------------------------------
__global__ void __launch_bounds__(256) k_emb2(const float* __restrict__ x,
                                              const float* __restrict__ pos)
{
    __shared__ float ps[32 * 36];
    __shared__ float xs[2][32 * 33];

    int bc = blockIdx.x;
    int c = bc % 3;
    int tid = threadIdx.x;

    {
        float4 pv = ((const float4*)(pos + c * 1024))[tid];
        int j = tid >> 3, d0 = (tid & 7) * 4;
        ps[(d0 + 0) * 36 + j] = pv.x;
        ps[(d0 + 1) * 36 + j] = pv.y;
        ps[(d0 + 2) * 36 + j] = pv.z;
        ps[(d0 + 3) * 36 + j] = pv.w;
    }

    const float* xb = x + (size_t)bc * 32768;
    float* ob = g_emb + (size_t)bc * 32768;
    int i  = tid >> 3, j0 = (tid & 7) * 4;
    int dd = tid >> 3, i4 = (tid & 7) * 4;

    for (int tg = 0; tg < 16; tg++) {
        float4 xv0 = ((const float4*)(xb + (size_t)(2 * tg)     * 1024))[tid];
        float4 xv1 = ((const float4*)(xb + (size_t)(2 * tg + 1) * 1024))[tid];
        __syncthreads();
        xs[0][dd * 33 + i4 + 0] = xv0.x; xs[0][dd * 33 + i4 + 1] = xv0.y;
        xs[0][dd * 33 + i4 + 2] = xv0.z; xs[0][dd * 33 + i4 + 3] = xv0.w;
        xs[1][dd * 33 + i4 + 0] = xv1.x; xs[1][dd * 33 + i4 + 1] = xv1.y;
        xs[1][dd * 33 + i4 + 2] = xv1.z; xs[1][dd * 33 + i4 + 3] = xv1.w;
        __syncthreads();

        u64 a00 = 0, a01 = 0, a10 = 0, a11 = 0;
#pragma unroll
        for (int d = 0; d < 32; d++) {
            ulonglong2 p = *(const ulonglong2*)(ps + d * 36 + j0);
            float x0 = xs[0][d * 33 + i];
            float x1 = xs[1][d * 33 + i];
            u64 x0p = pack2(x0, x0), x1p = pack2(x1, x1);
            a00 = fma2(x0p, p.x, a00); a01 = fma2(x0p, p.y, a01);
            a10 = fma2(x1p, p.x, a10); a11 = fma2(x1p, p.y, a11);
        }
        float b0, b1, b2, b3;
        unpack2(a00, b0, b1); unpack2(a01, b2, b3);
        *(float4*)(ob + (size_t)i * 1024 + (2 * tg) * 32 + j0) = make_float4(b0, b1, b2, b3);
        unpack2(a10, b0, b1); unpack2(a11, b2, b3);
        *(float4*)(ob + (size_t)i * 1024 + (2 * tg + 1) * 32 + j0) = make_float4(b0, b1, b2, b3);
    }
}

// ---------------------------------------------------------------------------
// K3 v6: y-branch with tensor-core QKV and W0 GEMMs (tf32 m16n8k8).
// 1 tile/warp. smem (dynamic): sWt[32x100] tf32 W^T | sW0t[32x36] tf32 W0^T |
// per-warp: st[1056] (E -> in-place residual) | qbuf[1056] (q -> o) | kvbuf[1024] (fp16 KV)
// Writes RESIDUAL (E + proj); LN+sigmoid in k_final.
// ---------------------------------------------------------------------------
__global__ void __launch_bounds__(128) k_attn_y6(
    const float* __restrict__ Wqvk, const float* __restrict__ W0, int base)
{
    extern __shared__ float sm[];
    unsigned* sWt  = (unsigned*)sm;          // 3200 (stride 100, [j][f])
    unsigned* sW0t = (unsigned*)sm + 3200;   // 1152 (stride 36, [ji][jo])

    int tid = threadIdx.x;
    int w = tid >> 5, lane = tid & 31;
    float* st   = sm + 4352 + w * 3136;      // 1056
    float* qbuf = st + 1056;                 // 1056
    float* kvbuf = qbuf + 1056;              // 1024 floats = 32 tok x 8 head x uint4

    int cid = base + blockIdx.x;
    int bc = cid >> 3;
    int ib = cid & 7;
    int c = bc % 3;

    // stage transposed tf32 weights (once per CTA)
    for (int k = tid; k < 3072; k += 128) {
        int f = k >> 5, j = k & 31;
        sWt[j * 100 + f] = tf32_(Wqvk[c * 3072 + k]);
    }
    for (int k = tid; k < 1024; k += 128) {
        int jo = k >> 5, ji = k & 31;
        sW0t[ji * 36 + jo] = tf32_(W0[c * 1024 + k]);
    }
    __syncthreads();

    int i = ib * 4 + w;
    const float* eg = g_emb + ((size_t)bc * 32 + i) * 1024;
    float* og       = g_sig + ((size_t)bc * 32 + i) * 1024;

    int gid = lane >> 2;     // groupID (row)
    int tig = lane & 3;      // threadID in group (col)

    // ---- stage E coalesced -> stride-33 ----
#pragma unroll
    for (int r = 0; r < 32; r++) st[r * 33 + lane] = eg[r * 32 + lane];
    __syncwarp();

    // ---- A fragments of E (2 m-tiles x 4 k-steps x 4 regs) ----
    unsigned aq[2][4][4];
#pragma unroll
    for (int m = 0; m < 2; m++)
#pragma unroll
        for (int kk = 0; kk < 4; kk++) {
            int r = m * 16 + gid, cc = kk * 8 + tig;
            aq[m][kk][0] = tf32_(st[r * 33 + cc]);
            aq[m][kk][1] = tf32_(st[(r + 8) * 33 + cc]);
            aq[m][kk][2] = tf32_(st[r * 33 + cc + 4]);
            aq[m][kk][3] = tf32_(st[(r + 8) * 33 + cc + 4]);
        }

    const float QS = 0.72134752044f;   // 0.5 * log2(e)
    __half* hp = (__half*)kvbuf;

    // ---- QKV GEMM: [32x32] @ [32x96], f = d*24 + wh*8 + h; n-tile n -> wh=n%3, d=n/3 ----
#pragma unroll
    for (int n = 0; n < 12; n++) {
        unsigned b[4][2];
#pragma unroll
        for (int kk = 0; kk < 4; kk++) {
            b[kk][0] = sWt[(kk * 8 + tig) * 100 + n * 8 + gid];
            b[kk][1] = sWt[(kk * 8 + tig + 4) * 100 + n * 8 + gid];
        }
        int wh = n % 3, d = n / 3;
        int h = 2 * tig;
#pragma unroll
        for (int m = 0; m < 2; m++) {
            float cc[4] = {0.f, 0.f, 0.f, 0.f};
#pragma unroll
            for (int kk = 0; kk < 4; kk++) mma_(cc, aq[m][kk], b[kk]);
            int t = m * 16 + gid;
            if (wh == 0) {
                qbuf[t * 33 + h * 4 + d]           = cc[0] * QS;
                qbuf[t * 33 + (h + 1) * 4 + d]     = cc[1] * QS;
                qbuf[(t + 8) * 33 + h * 4 + d]       = cc[2] * QS;
                qbuf[(t + 8) * 33 + (h + 1) * 4 + d] = cc[3] * QS;
            } else {
                int off = (wh == 1) ? 0 : 4;
                hp[(t * 8 + h) * 8 + off + d]           = __float2half_rn(cc[0]);
                hp[(t * 8 + h + 1) * 8 + off + d]       = __float2half_rn(cc[1]);
                hp[((t + 8) * 8 + h) * 8 + off + d]     = __float2half_rn(cc[2]);
                hp[((t + 8) * 8 + h + 1) * 8 + off + d] = __float2half_rn(cc[3]);
            }
        }
    }
    __syncwarp();

    // ---- per-head softmax(exp2) + AV; o overwrites q slot in qbuf ----
#pragma unroll 1
    for (int h = 0; h < 8; h++) {
        float q0 = qbuf[lane * 33 + 4 * h + 0];
        float q1 = qbuf[lane * 33 + 4 * h + 1];
        float q2 = qbuf[lane * 33 + 4 * h + 2];
        float q3 = qbuf[lane * 33 + 4 * h + 3];
        u64 q01 = pack2(q0, q1), q23 = pack2(q2, q3);

        float sum = 0.f;
        u64 a01 = 0, a23 = 0;
#pragma unroll 8
        for (int s = 0; s < 32; s++) {
            uint4 u = *(uint4*)(kvbuf + (s * 8 + h) * 4);   // uniform broadcast
            u64 t = fma2(q23, f2u(u2f2(u.y)), mul2(q01, f2u(u2f2(u.x))));
            float ta, tb; unpack2(t, ta, tb);
            float p = ex2_(ta + tb);
            sum += p;
            u64 p2 = pack2(p, p);
            a01 = fma2(p2, f2u(u2f2(u.z)), a01);
            a23 = fma2(p2, f2u(u2f2(u.w)), a23);
        }
        float inv = 1.f / sum;
        float oa, ob, oc, od;
        unpack2(a01, oa, ob); unpack2(a23, oc, od);
        qbuf[lane * 33 + 4 * h + 0] = oa * inv;
        qbuf[lane * 33 + 4 * h + 1] = ob * inv;
        qbuf[lane * 33 + 4 * h + 2] = oc * inv;
        qbuf[lane * 33 + 4 * h + 3] = od * inv;
    }
    __syncwarp();   // o matrix complete before cross-lane fragment reads

    // ---- W0 GEMM: [32x32] @ [32x32] + residual (in-place into st) ----
    unsigned ao[2][4][4];
#pragma unroll
    for (int m = 0; m < 2; m++)
#pragma unroll
        for (int kk = 0; kk < 4; kk++) {
            int r = m * 16 + gid, cc = kk * 8 + tig;
            ao[m][kk][0] = tf32_(qbuf[r * 33 + cc]);
            ao[m][kk][1] = tf32_(qbuf[(r + 8) * 33 + cc]);
            ao[m][kk][2] = tf32_(qbuf[r * 33 + cc + 4]);
            ao[m][kk][3] = tf32_(qbuf[(r + 8) * 33 + cc + 4]);
        }

#pragma unroll
    for (int n = 0; n < 4; n++) {
        unsigned b[4][2];
#pragma unroll
        for (int kk = 0; kk < 4; kk++) {
            b[kk][0] = sW0t[(kk * 8 + tig) * 36 + n * 8 + gid];
            b[kk][1] = sW0t[(kk * 8 + tig + 4) * 36 + n * 8 + gid];
        }
#pragma unroll
        for (int m = 0; m < 2; m++) {
            float cc[4] = {0.f, 0.f, 0.f, 0.f};
#pragma unroll
            for (int kk = 0; kk < 4; kk++) mma_(cc, ao[m][kk], b[kk]);
            int t = m * 16 + gid;
            int f0 = n * 8 + 2 * tig;
            st[t * 33 + f0]           += cc[0];
            st[t * 33 + f0 + 1]       += cc[1];
            st[(t + 8) * 33 + f0]     += cc[2];
            st[(t + 8) * 33 + f0 + 1] += cc[3];
        }
    }
    __syncwarp();

    // ---- coalesced store of residual ----
#pragma unroll
    for (int r = 0; r < 32; r++) og[r * 32 + lane] = st[r * 33 + lane];
}

// ---------------------------------------------------------------------------
// x-branch full warp attention (unchanged, fp32)
// ---------------------------------------------------------------------------
__device__ __forceinline__ void warp_attn_full(
    int lane,
    const float* __restrict__ eg, float* __restrict__ og,
    const float* __restrict__ sW, const float* __restrict__ sW0,
    const float* __restrict__ sgb, float* __restrict__ skv)
{
    u64 e2[16];
    {
        const ulonglong2* ep = (const ulonglong2*)(eg + lane * 32);
#pragma unroll
        for (int j = 0; j < 8; j++) { ulonglong2 v = ep[j]; e2[2*j] = v.x; e2[2*j+1] = v.y; }
    }
    float rr[32];
#pragma unroll
    for (int j = 0; j < 16; j++) unpack2(e2[j], rr[2*j], rr[2*j+1]);

#pragma unroll 1
    for (int h = 0; h < 8; h++) {
        float q[4], kk[4], vv[4];
#pragma unroll
        for (int d = 0; d < 4; d++) {
            const ulonglong2* wq = (const ulonglong2*)(sW + (d * 24 + h)      * 32);
            const ulonglong2* wk = (const ulonglong2*)(sW + (d * 24 + 8 + h)  * 32);
            const ulonglong2* wv = (const ulonglong2*)(sW + (d * 24 + 16 + h) * 32);
            u64 aq = 0, ak = 0, av = 0;
#pragma unroll
            for (int j = 0; j < 8; j++) {
                ulonglong2 ww;
                ww = wq[j]; aq = fma2(e2[2*j+1], ww.y, fma2(e2[2*j], ww.x, aq));
                ww = wk[j]; ak = fma2(e2[2*j+1], ww.y, fma2(e2[2*j], ww.x, ak));
                ww = wv[j]; av = fma2(e2[2*j+1], ww.y, fma2(e2[2*j], ww.x, av));
            }
            float a, b;
            unpack2(aq, a, b); q[d]  = (a + b) * 0.5f;
            unpack2(ak, a, b); kk[d] = a + b;
            unpack2(av, a, b); vv[d] = a + b;
        }
        *(float4*)(skv + lane * 12)     = make_float4(kk[0], kk[1], kk[2], kk[3]);
        *(float4*)(skv + lane * 12 + 4) = make_float4(vv[0], vv[1], vv[2], vv[3]);
        u64 q01 = pack2(q[0], q[1]), q23 = pack2(q[2], q[3]);
        __syncwarp();

        float sum = 0.f;
        u64 a01 = 0, a23 = 0;
#pragma unroll
        for (int s = 0; s < 32; s++) {
            ulonglong2 k2 = *(const ulonglong2*)(skv + s * 12);
            ulonglong2 v2 = *(const ulonglong2*)(skv + s * 12 + 4);
            u64 t = fma2(q23, k2.y, mul2(q01, k2.x));
            float ta, tb; unpack2(t, ta, tb);
            float p = __expf(ta + tb);
            sum += p;
            u64 p2 = pack2(p, p);
            a01 = fma2(p2, v2.x, a01);
            a23 = fma2(p2, v2.y, a23);
        }
        __syncwarp();
        float inv = 1.f / sum;
        float oa, ob, oc, od;
        unpack2(a01, oa, ob); unpack2(a23, oc, od);
        u64 o01 = pack2(oa * inv, ob * inv), o23 = pack2(oc * inv, od * inv);

        const float* w0h = sW0 + 4 * h;
#pragma unroll
        for (int j = 0; j < 32; j += 2) {
            ulonglong2 wa = *(const ulonglong2*)(w0h + j * 32);
            ulonglong2 wb = *(const ulonglong2*)(w0h + (j + 1) * 32);
            u64 ra = fma2(o23, wa.y, mul2(o01, wa.x));
            u64 rb = fma2(o23, wb.y, mul2(o01, wb.x));
            float xa, xb;
            unpack2(ra, xa, xb); rr[j]     += xa + xb;
            unpack2(rb, xa, xb); rr[j + 1] += xa + xb;
        }
    }

    float s1 = 0.f;
#pragma unroll
    for (int j = 0; j < 32; j++) s1 += rr[j];
    float mu = s1 * 0.03125f;
    float sq = 0.f;
#pragma unroll
    for (int j = 0; j < 32; j++) { float d = rr[j] - mu; sq = fmaf(d, d, sq); }
    float rstd = rsqrtf(sq * 0.03125f + 1e-5f);

    float* po = og + lane * 32;
#pragma unroll
    for (int j = 0; j < 32; j += 4) {
        float4 v;
        v.x = sigmoid_((rr[j]     - mu) * rstd * sgb[j]     + sgb[32 + j]);
        v.y = sigmoid_((rr[j + 1] - mu) * rstd * sgb[j + 1] + sgb[33 + j]);
        v.z = sigmoid_((rr[j + 2] - mu) * rstd * sgb[j + 2] + sgb[34 + j]);
        v.w = sigmoid_((rr[j + 3] - mu) * rstd * sgb[j + 3] + sgb[35 + j]);
        *(float4*)(po + j) = v;
    }
}

__global__ void __launch_bounds__(128) k_attn_x2(
    const float* __restrict__ Wqvk, const float* __restrict__ W0,
    const float* __restrict__ g, const float* __restrict__ b, int nb4)
{
    __shared__ float sW[3072];
    __shared__ float sW0[1024];
    __shared__ float sgb[64];
    __shared__ float tiles[4 * 384];

    int tid = threadIdx.x;
    int w = tid >> 5, lane = tid & 31;
    int c  = blockIdx.x / nb4;
    int bq = blockIdx.x % nb4;

    for (int k = tid; k < 768; k += 128) ((float4*)sW)[k]  = ((const float4*)(Wqvk + c * 3072))[k];
    for (int k = tid; k < 256; k += 128) ((float4*)sW0)[k] = ((const float4*)(W0 + c * 1024))[k];
    if (tid < 32) { sgb[tid] = g[tid]; sgb[32 + tid] = b[tid]; }
    __syncthreads();

    int bb = bq * 4 + w;
    const float* eg = g_emb + (((size_t)bb * 3 + 2) * 32 + 31) * 1024;
    float* og = g_sg2 + ((size_t)bb * 3 + c) * 1024;
    warp_attn_full(lane, eg, og, sW, sW0, sgb, tiles + w * 384);
}

// ---------------------------------------------------------------------------
// K4 (unchanged): gate_y = sigmoid(LN(res)); out = sg2 * gate_y * x.
// ---------------------------------------------------------------------------
__global__ void __launch_bounds__(256) k_final(const float* __restrict__ x,
                                               const float* __restrict__ gam,
                                               const float* __restrict__ bet,
                                               float* __restrict__ out)
{
    __shared__ float gs[32 * 33];
    __shared__ float ss[32];
    int bct = blockIdx.x;
    int t = bct & 31;
    int bc = bct >> 5;
    int tid = threadIdx.x;

    int i = tid >> 3, j0 = (tid & 7) * 4;
    size_t base = ((size_t)bc * 32 + i) * 1024 + t * 32 + j0;
    float4 v = *(const float4*)(g_sig + base);

    float s1 = v.x + v.y + v.z + v.w;
    float s2 = fmaf(v.x, v.x, fmaf(v.y, v.y, fmaf(v.z, v.z, v.w * v.w)));
#pragma unroll
    for (int m = 1; m < 8; m <<= 1) {
        s1 += __shfl_xor_sync(0xffffffffu, s1, m);
        s2 += __shfl_xor_sync(0xffffffffu, s2, m);
    }
    float mu = s1 * 0.03125f;
    float var = fmaf(-mu, mu, s2 * 0.03125f);
    float rstd = rsqrtf(var + 1e-5f);

    float4 gm = *(const float4*)(gam + j0);
    float4 bt = *(const float4*)(bet + j0);
    gs[i * 33 + j0 + 0] = sigmoid_((v.x - mu) * rstd * gm.x + bt.x);
    gs[i * 33 + j0 + 1] = sigmoid_((v.y - mu) * rstd * gm.y + bt.y);
    gs[i * 33 + j0 + 2] = sigmoid_((v.z - mu) * rstd * gm.z + bt.z);
    gs[i * 33 + j0 + 3] = sigmoid_((v.w - mu) * rstd * gm.w + bt.w);
    if (tid < 32) ss[tid] = g_sg2[(size_t)bc * 1024 + tid * 32 + t];
    __syncthreads();

    float4 xv = ((const float4*)(x + (size_t)bct * 1024))[tid];
    int jj = tid >> 3, i0 = (tid & 7) * 4;
    float4 ov;
    ov.x = ss[i0 + 0] * gs[(i0 + 0) * 33 + jj] * xv.x;
    ov.y = ss[i0 + 1] * gs[(i0 + 1) * 33 + jj] * xv.y;
    ov.z = ss[i0 + 2] * gs[(i0 + 2) * 33 + jj] * xv.z;
    ov.w = ss[i0 + 3] * gs[(i0 + 3) * 33 + jj] * xv.w;
    ((float4*)(out + (size_t)bct * 1024))[tid] = ov;
}

// ---------------------------------------------------------------------------
extern "C" void kernel_launch(void* const* d_in, const int* in_sizes, int n_in,
                              void* d_out, int out_size)
{
    const float* x   = (const float*)d_in[0];
    const float* pos = (const float*)d_in[1];
    const float* Wqy = (const float*)d_in[2];
    const float* W0y = (const float*)d_in[3];
    const float* gy  = (const float*)d_in[4];
    const float* by  = (const float*)d_in[5];
    const float* Wqx = (const float*)d_in[6];
    const float* W0x = (const float*)d_in[7];
    const float* gx  = (const float*)d_in[8];
    const float* bx  = (const float*)d_in[9];
    float* out = (float*)d_out;

    int B = in_sizes[0] / 98304;  // 3*32*32*32

    const int SMEM_Y = (4352 + 4 * 3136) * 4;   // 67,584 B
    cudaFuncSetAttribute(k_attn_y6, cudaFuncAttributeMaxDynamicSharedMemorySize, SMEM_Y);

    int nY = B * 24;          // CTAs (4 tiles each)
    int h1 = nY / 2;
    int nb4 = B / 4;

    k_emb2<<<B * 3, 256>>>(x, pos);
    k_attn_x2<<<3 * nb4, 128>>>(Wqx, W0x, gx, bx, nb4);
    k_attn_y6<<<h1, 128, SMEM_Y>>>(Wqy, W0y, 0);
    k_attn_y6<<<nY - h1, 128, SMEM_Y>>>(Wqy, W0y, h1);
    k_final<<<B * 96, 256>>>(x, gy, by, out);
}

// round 10
// speedup vs baseline: 2.2529x; 1.1032x over previous
#include <cuda_runtime.h>
#include <cuda_fp16.h>

typedef unsigned long long u64;

#define B_MAX 256

__device__ float g_emb[B_MAX * 3 * 32 * 32 * 32];  // [b][c][i][t][j]
__device__ float g_sig[B_MAX * 3 * 32 * 32 * 32];  // y-branch residual (emb + proj)
__device__ float g_sg2[B_MAX * 3 * 32 * 32];       // sigmoid(LN(x-branch))

// ---------------- packed f32x2 + misc helpers ----------------
__device__ __forceinline__ u64 pack2(float lo, float hi) {
    u64 r; asm("mov.b64 %0, {%1, %2};" : "=l"(r) : "f"(lo), "f"(hi)); return r;
}
__device__ __forceinline__ void unpack2(u64 v, float& lo, float& hi) {
    asm("mov.b64 {%0, %1}, %2;" : "=f"(lo), "=f"(hi) : "l"(v));
}
__device__ __forceinline__ u64 fma2(u64 a, u64 b, u64 c) {
    u64 d; asm("fma.rn.f32x2 %0, %1, %2, %3;" : "=l"(d) : "l"(a), "l"(b), "l"(c)); return d;
}
__device__ __forceinline__ u64 mul2(u64 a, u64 b) {
    u64 d; asm("mul.rn.f32x2 %0, %1, %2;" : "=l"(d) : "l"(a), "l"(b)); return d;
}
__device__ __forceinline__ u64 f2u(float2 v) {
    u64 r; asm("mov.b64 %0, {%1, %2};" : "=l"(r) : "f"(v.x), "f"(v.y)); return r;
}
__device__ __forceinline__ unsigned h2u(__half2 h) { return *(unsigned*)&h; }
__device__ __forceinline__ float2 u2f2(unsigned u) { __half2 h = *(__half2*)&u; return __half22float2(h); }
__device__ __forceinline__ float ex2_(float x) {
    float r; asm("ex2.approx.f32 %0, %1;" : "=f"(r) : "f"(x)); return r;
}
__device__ __forceinline__ float sigmoid_(float v) { return 1.0f / (1.0f + __expf(-v)); }
__device__ __forceinline__ unsigned tf32_(float x) {
    unsigned u; asm("cvt.rna.tf32.f32 %0, %1;" : "=r"(u) : "f"(x)); return u;
}
__device__ __forceinline__ void mma_(float c[4], const unsigned a[4], const unsigned b[2]) {
    asm volatile(
        "mma.sync.aligned.m16n8k8.row.col.f32.tf32.tf32.f32 "
        "{%0,%1,%2,%3}, {%4,%5,%6,%7}, {%8,%9}, {%0,%1,%2,%3};"
        : "+f"(c[0]), "+f"(c[1]), "+f"(c[2]), "+f"(c[3])
        : "r"(a[0]), "r"(a[1]), "r"(a[2]), "r"(a[3]), "r"(b[0]), "r"(b[1]));
}

// strides chosen for bank-conflict-freedom (see analysis):
#define ST 37     // st/qbuf row stride: 37 = 5 mod 32 -> 5*gid + tig bijective-enough
#define WS 104    // sWt row stride: 8 mod 32 -> 8*tig + gid bijective
#define W0S 40    // sW0t row stride: 8 mod 32
#define KVS 36    // kv token stride in 32-bit words (4 words per (t,h), 16B aligned)

// ---------------------------------------------------------------------------
// K1 v2 (unchanged, verified)
// ---------------------------------------------------------------------------
__global__ void __launch_bounds__(256) k_emb2(const float* __restrict__ x,
                                              const float* __restrict__ pos)
{
    __shared__ float ps[32 * 36];
    __shared__ float xs[2][32 * 33];

    int bc = blockIdx.x;
    int c = bc % 3;
    int tid = threadIdx.x;

    {
        float4 pv = ((const float4*)(pos + c * 1024))[tid];
        int j = tid >> 3, d0 = (tid & 7) * 4;
        ps[(d0 + 0) * 36 + j] = pv.x;
        ps[(d0 + 1) * 36 + j] = pv.y;
        ps[(d0 + 2) * 36 + j] = pv.z;
        ps[(d0 + 3) * 36 + j] = pv.w;
    }

    const float* xb = x + (size_t)bc * 32768;
    float* ob = g_emb + (size_t)bc * 32768;
    int i  = tid >> 3, j0 = (tid & 7) * 4;
    int dd = tid >> 3, i4 = (tid & 7) * 4;

    for (int tg = 0; tg < 16; tg++) {
        float4 xv0 = ((const float4*)(xb + (size_t)(2 * tg)     * 1024))[tid];
        float4 xv1 = ((const float4*)(xb + (size_t)(2 * tg + 1) * 1024))[tid];
        __syncthreads();
        xs[0][dd * 33 + i4 + 0] = xv0.x; xs[0][dd * 33 + i4 + 1] = xv0.y;
        xs[0][dd * 33 + i4 + 2] = xv0.z; xs[0][dd * 33 + i4 + 3] = xv0.w;
        xs[1][dd * 33 + i4 + 0] = xv1.x; xs[1][dd * 33 + i4 + 1] = xv1.y;
        xs[1][dd * 33 + i4 + 2] = xv1.z; xs[1][dd * 33 + i4 + 3] = xv1.w;
        __syncthreads();

        u64 a00 = 0, a01 = 0, a10 = 0, a11 = 0;
#pragma unroll
        for (int d = 0; d < 32; d++) {
            ulonglong2 p = *(const ulonglong2*)(ps + d * 36 + j0);
            float x0 = xs[0][d * 33 + i];
            float x1 = xs[1][d * 33 + i];
            u64 x0p = pack2(x0, x0), x1p = pack2(x1, x1);
            a00 = fma2(x0p, p.x, a00); a01 = fma2(x0p, p.y, a01);
            a10 = fma2(x1p, p.x, a10); a11 = fma2(x1p, p.y, a11);
        }
        float b0, b1, b2, b3;
        unpack2(a00, b0, b1); unpack2(a01, b2, b3);
        *(float4*)(ob + (size_t)i * 1024 + (2 * tg) * 32 + j0) = make_float4(b0, b1, b2, b3);
        unpack2(a10, b0, b1); unpack2(a11, b2, b3);
        *(float4*)(ob + (size_t)i * 1024 + (2 * tg + 1) * 32 + j0) = make_float4(b0, b1, b2, b3);
    }
}

// ---------------------------------------------------------------------------
// K3 v7: tensor-core QKV/W0 with conflict-free smem strides and d-packed
// half2 KV word stores. 1 tile/warp.
// Per-warp: st[32*ST] | qbuf[32*ST] | kvb[32*KVS words]
// ---------------------------------------------------------------------------
__global__ void __launch_bounds__(128) k_attn_y7(
    const float* __restrict__ Wqvk, const float* __restrict__ W0, int base)
{
    extern __shared__ float sm[];
    unsigned* sWt  = (unsigned*)sm;                 // 32*WS
    unsigned* sW0t = (unsigned*)sm + 32 * WS;       // 32*W0S

    const int WB = 32 * WS + 32 * W0S;              // weight words
    const int PW = 2 * 32 * ST + 32 * KVS;          // per-warp floats

    int tid = threadIdx.x;
    int w = tid >> 5, lane = tid & 31;
    float* st   = sm + WB + w * PW;
    float* qbuf = st + 32 * ST;
    float* kvb  = qbuf + 32 * ST;
    unsigned* kvw = (unsigned*)kvb;

    int cid = base + blockIdx.x;
    int bc = cid >> 3;
    int ib = cid & 7;
    int c = bc % 3;

    // stage transposed tf32 weights (once per CTA)
    for (int k = tid; k < 3072; k += 128) {
        int f = k >> 5, j = k & 31;
        sWt[j * WS + f] = tf32_(Wqvk[c * 3072 + k]);
    }
    for (int k = tid; k < 1024; k += 128) {
        int jo = k >> 5, ji = k & 31;
        sW0t[ji * W0S + jo] = tf32_(W0[c * 1024 + k]);
    }
    __syncthreads();

    int i = ib * 4 + w;
    const float* eg = g_emb + ((size_t)bc * 32 + i) * 1024;
    float* og       = g_sig + ((size_t)bc * 32 + i) * 1024;

    int gid = lane >> 2;     // fragment row group
    int tig = lane & 3;      // fragment col group

    // ---- stage E coalesced -> stride-ST ----
#pragma unroll
    for (int r = 0; r < 32; r++) st[r * ST + lane] = eg[r * 32 + lane];
    __syncwarp();

    // ---- A fragments of E ----
    unsigned aq[2][4][4];
#pragma unroll
    for (int m = 0; m < 2; m++)
#pragma unroll
        for (int kk = 0; kk < 4; kk++) {
            int r = m * 16 + gid, cc = kk * 8 + tig;
            aq[m][kk][0] = tf32_(st[r * ST + cc]);
            aq[m][kk][1] = tf32_(st[(r + 8) * ST + cc]);
            aq[m][kk][2] = tf32_(st[r * ST + cc + 4]);
            aq[m][kk][3] = tf32_(st[(r + 8) * ST + cc + 4]);
        }

    const float QS = 0.72134752044f;   // 0.5 * log2(e)

    // ---- QKV GEMM, d-pair major so KV packs into half2 words ----
#pragma unroll
    for (int dp = 0; dp < 2; dp++) {
        float cck[2][2][4], ccv[2][2][4];   // [dd][m][reg]
#pragma unroll
        for (int dd = 0; dd < 2; dd++) {
            int d = 2 * dp + dd;
#pragma unroll
            for (int wh = 0; wh < 3; wh++) {
                int n = 3 * d + wh;     // n-tile: f = d*24 + wh*8 + h
                unsigned b[4][2];
#pragma unroll
                for (int kk = 0; kk < 4; kk++) {
                    b[kk][0] = sWt[(kk * 8 + tig) * WS + n * 8 + gid];
                    b[kk][1] = sWt[(kk * 8 + tig + 4) * WS + n * 8 + gid];
                }
#pragma unroll
                for (int m = 0; m < 2; m++) {
                    float cc[4] = {0.f, 0.f, 0.f, 0.f};
#pragma unroll
                    for (int kk = 0; kk < 4; kk++) mma_(cc, aq[m][kk], b[kk]);
                    if (wh == 0) {
                        int t = m * 16 + gid, h = 2 * tig;
                        qbuf[t * ST + h * 4 + d]           = cc[0] * QS;
                        qbuf[t * ST + (h + 1) * 4 + d]     = cc[1] * QS;
                        qbuf[(t + 8) * ST + h * 4 + d]       = cc[2] * QS;
                        qbuf[(t + 8) * ST + (h + 1) * 4 + d] = cc[3] * QS;
                    } else if (wh == 1) {
#pragma unroll
                        for (int r2 = 0; r2 < 4; r2++) cck[dd][m][r2] = cc[r2];
                    } else {
#pragma unroll
                        for (int r2 = 0; r2 < 4; r2++) ccv[dd][m][r2] = cc[r2];
                    }
                }
            }
        }
        // pack (d, d+1) half2 and store words: kv slot (t,h) = 4 words [k01,k23,v01,v23]
#pragma unroll
        for (int m = 0; m < 2; m++)
#pragma unroll
            for (int rh = 0; rh < 2; rh++)
#pragma unroll
                for (int p = 0; p < 2; p++) {
                    int reg = p + 2 * rh;
                    int t = m * 16 + rh * 8 + gid;
                    int h = 2 * tig + p;
                    unsigned kw = h2u(__floats2half2_rn(cck[0][m][reg], cck[1][m][reg]));
                    unsigned vw = h2u(__floats2half2_rn(ccv[0][m][reg], ccv[1][m][reg]));
                    kvw[t * KVS + 4 * h + dp]     = kw;
                    kvw[t * KVS + 4 * h + 2 + dp] = vw;
                }
    }
    __syncwarp();

    // ---- per-head softmax(exp2) + AV; o overwrites q slot in qbuf ----
#pragma unroll 1
    for (int h = 0; h < 8; h++) {
        float q0 = qbuf[lane * ST + 4 * h + 0];
        float q1 = qbuf[lane * ST + 4 * h + 1];
        float q2 = qbuf[lane * ST + 4 * h + 2];
        float q3 = qbuf[lane * ST + 4 * h + 3];
        u64 q01 = pack2(q0, q1), q23 = pack2(q2, q3);

        float sum = 0.f;
        u64 a01 = 0, a23 = 0;
#pragma unroll 8
        for (int s = 0; s < 32; s++) {
            uint4 u = *(uint4*)(kvw + s * KVS + 4 * h);   // uniform broadcast, 16B aligned
            u64 t = fma2(q23, f2u(u2f2(u.y)), mul2(q01, f2u(u2f2(u.x))));
            float ta, tb; unpack2(t, ta, tb);
            float p = ex2_(ta + tb);
            sum += p;
            u64 p2 = pack2(p, p);
            a01 = fma2(p2, f2u(u2f2(u.z)), a01);
            a23 = fma2(p2, f2u(u2f2(u.w)), a23);
        }
        float inv = 1.f / sum;
        float oa, ob, oc, od;
        unpack2(a01, oa, ob); unpack2(a23, oc, od);
        qbuf[lane * ST + 4 * h + 0] = oa * inv;
        qbuf[lane * ST + 4 * h + 1] = ob * inv;
        qbuf[lane * ST + 4 * h + 2] = oc * inv;
        qbuf[lane * ST + 4 * h + 3] = od * inv;
    }
    __syncwarp();   // o matrix complete before cross-lane fragment reads

    // ---- W0 GEMM + residual (in-place into st) ----
    unsigned ao[2][4][4];
#pragma unroll
    for (int m = 0; m < 2; m++)
#pragma unroll
        for (int kk = 0; kk < 4; kk++) {
            int r = m * 16 + gid, cc = kk * 8 + tig;
            ao[m][kk][0] = tf32_(qbuf[r * ST + cc]);
            ao[m][kk][1] = tf32_(qbuf[(r + 8) * ST + cc]);
            ao[m][kk][2] = tf32_(qbuf[r * ST + cc + 4]);
            ao[m][kk][3] = tf32_(qbuf[(r + 8) * ST + cc + 4]);
        }

#pragma unroll
    for (int n = 0; n < 4; n++) {
        unsigned b[4][2];
#pragma unroll
        for (int kk = 0; kk < 4; kk++) {
            b[kk][0] = sW0t[(kk * 8 + tig) * W0S + n * 8 + gid];
            b[kk][1] = sW0t[(kk * 8 + tig + 4) * W0S + n * 8 + gid];
        }
#pragma unroll
        for (int m = 0; m < 2; m++) {
            float cc[4] = {0.f, 0.f, 0.f, 0.f};
#pragma unroll
            for (int kk = 0; kk < 4; kk++) mma_(cc, ao[m][kk], b[kk]);
            int t = m * 16 + gid;
            int f0 = n * 8 + 2 * tig;
            st[t * ST + f0]           += cc[0];
            st[t * ST + f0 + 1]       += cc[1];
            st[(t + 8) * ST + f0]     += cc[2];
            st[(t + 8) * ST + f0 + 1] += cc[3];
        }
    }
    __syncwarp();

    // ---- coalesced store of residual ----
#pragma unroll
    for (int r = 0; r < 32; r++) og[r * 32 + lane] = st[r * ST + lane];
}

// ---------------------------------------------------------------------------
// x-branch full warp attention (unchanged, fp32)
// ---------------------------------------------------------------------------
__device__ __forceinline__ void warp_attn_full(
    int lane,
    const float* __restrict__ eg, float* __restrict__ og,
    const float* __restrict__ sW, const float* __restrict__ sW0,
    const float* __restrict__ sgb, float* __restrict__ skv)
{
    u64 e2[16];
    {
        const ulonglong2* ep = (const ulonglong2*)(eg + lane * 32);
#pragma unroll
        for (int j = 0; j < 8; j++) { ulonglong2 v = ep[j]; e2[2*j] = v.x; e2[2*j+1] = v.y; }
    }
    float rr[32];
#pragma unroll
    for (int j = 0; j < 16; j++) unpack2(e2[j], rr[2*j], rr[2*j+1]);

#pragma unroll 1
    for (int h = 0; h < 8; h++) {
        float q[4], kk[4], vv[4];
#pragma unroll
        for (int d = 0; d < 4; d++) {
            const ulonglong2* wq = (const ulonglong2*)(sW + (d * 24 + h)      * 32);
            const ulonglong2* wk = (const ulonglong2*)(sW + (d * 24 + 8 + h)  * 32);
            const ulonglong2* wv = (const ulonglong2*)(sW + (d * 24 + 16 + h) * 32);
            u64 aq = 0, ak = 0, av = 0;
#pragma unroll
            for (int j = 0; j < 8; j++) {
                ulonglong2 ww;
                ww = wq[j]; aq = fma2(e2[2*j+1], ww.y, fma2(e2[2*j], ww.x, aq));
                ww = wk[j]; ak = fma2(e2[2*j+1], ww.y, fma2(e2[2*j], ww.x, ak));
                ww = wv[j]; av = fma2(e2[2*j+1], ww.y, fma2(e2[2*j], ww.x, av));
            }
            float a, b;
            unpack2(aq, a, b); q[d]  = (a + b) * 0.5f;
            unpack2(ak, a, b); kk[d] = a + b;
            unpack2(av, a, b); vv[d] = a + b;
        }
        *(float4*)(skv + lane * 12)     = make_float4(kk[0], kk[1], kk[2], kk[3]);
        *(float4*)(skv + lane * 12 + 4) = make_float4(vv[0], vv[1], vv[2], vv[3]);
        u64 q01 = pack2(q[0], q[1]), q23 = pack2(q[2], q[3]);
        __syncwarp();

        float sum = 0.f;
        u64 a01 = 0, a23 = 0;
#pragma unroll
        for (int s = 0; s < 32; s++) {
            ulonglong2 k2 = *(const ulonglong2*)(skv + s * 12);
            ulonglong2 v2 = *(const ulonglong2*)(skv + s * 12 + 4);
            u64 t = fma2(q23, k2.y, mul2(q01, k2.x));
            float ta, tb; unpack2(t, ta, tb);
            float p = __expf(ta + tb);
            sum += p;
            u64 p2 = pack2(p, p);
            a01 = fma2(p2, v2.x, a01);
            a23 = fma2(p2, v2.y, a23);
        }
        __syncwarp();
        float inv = 1.f / sum;
        float oa, ob, oc, od;
        unpack2(a01, oa, ob); unpack2(a23, oc, od);
        u64 o01 = pack2(oa * inv, ob * inv), o23 = pack2(oc * inv, od * inv);

        const float* w0h = sW0 + 4 * h;
#pragma unroll
        for (int j = 0; j < 32; j += 2) {
            ulonglong2 wa = *(const ulonglong2*)(w0h + j * 32);
            ulonglong2 wb = *(const ulonglong2*)(w0h + (j + 1) * 32);
            u64 ra = fma2(o23, wa.y, mul2(o01, wa.x));
            u64 rb = fma2(o23, wb.y, mul2(o01, wb.x));
            float xa, xb;
            unpack2(ra, xa, xb); rr[j]     += xa + xb;
            unpack2(rb, xa, xb); rr[j + 1] += xa + xb;
        }
    }

    float s1 = 0.f;
#pragma unroll
    for (int j = 0; j < 32; j++) s1 += rr[j];
    float mu = s1 * 0.03125f;
    float sq = 0.f;
#pragma unroll
    for (int j = 0; j < 32; j++) { float d = rr[j] - mu; sq = fmaf(d, d, sq); }
    float rstd = rsqrtf(sq * 0.03125f + 1e-5f);

    float* po = og + lane * 32;
#pragma unroll
    for (int j = 0; j < 32; j += 4) {
        float4 v;
        v.x = sigmoid_((rr[j]     - mu) * rstd * sgb[j]     + sgb[32 + j]);
        v.y = sigmoid_((rr[j + 1] - mu) * rstd * sgb[j + 1] + sgb[33 + j]);
        v.z = sigmoid_((rr[j + 2] - mu) * rstd * sgb[j + 2] + sgb[34 + j]);
        v.w = sigmoid_((rr[j + 3] - mu) * rstd * sgb[j + 3] + sgb[35 + j]);
        *(float4*)(po + j) = v;
    }
}

__global__ void __launch_bounds__(128) k_attn_x2(
    const float* __restrict__ Wqvk, const float* __restrict__ W0,
    const float* __restrict__ g, const float* __restrict__ b, int nb4)
{
    __shared__ float sW[3072];
    __shared__ float sW0[1024];
    __shared__ float sgb[64];
    __shared__ float tiles[4 * 384];

    int tid = threadIdx.x;
    int w = tid >> 5, lane = tid & 31;
    int c  = blockIdx.x / nb4;
    int bq = blockIdx.x % nb4;

    for (int k = tid; k < 768; k += 128) ((float4*)sW)[k]  = ((const float4*)(Wqvk + c * 3072))[k];
    for (int k = tid; k < 256; k += 128) ((float4*)sW0)[k] = ((const float4*)(W0 + c * 1024))[k];
    if (tid < 32) { sgb[tid] = g[tid]; sgb[32 + tid] = b[tid]; }
    __syncthreads();

    int bb = bq * 4 + w;
    const float* eg = g_emb + (((size_t)bb * 3 + 2) * 32 + 31) * 1024;
    float* og = g_sg2 + ((size_t)bb * 3 + c) * 1024;
    warp_attn_full(lane, eg, og, sW, sW0, sgb, tiles + w * 384);
}

// ---------------------------------------------------------------------------
// K4 (unchanged): gate_y = sigmoid(LN(res)); out = sg2 * gate_y * x.
// ---------------------------------------------------------------------------
__global__ void __launch_bounds__(256) k_final(const float* __restrict__ x,
                                               const float* __restrict__ gam,
                                               const float* __restrict__ bet,
                                               float* __restrict__ out)
{
    __shared__ float gs[32 * 33];
    __shared__ float ss[32];
    int bct = blockIdx.x;
    int t = bct & 31;
    int bc = bct >> 5;
    int tid = threadIdx.x;

    int i = tid >> 3, j0 = (tid & 7) * 4;
    size_t base = ((size_t)bc * 32 + i) * 1024 + t * 32 + j0;
    float4 v = *(const float4*)(g_sig + base);

    float s1 = v.x + v.y + v.z + v.w;
    float s2 = fmaf(v.x, v.x, fmaf(v.y, v.y, fmaf(v.z, v.z, v.w * v.w)));
#pragma unroll
    for (int m = 1; m < 8; m <<= 1) {
        s1 += __shfl_xor_sync(0xffffffffu, s1, m);
        s2 += __shfl_xor_sync(0xffffffffu, s2, m);
    }
    float mu = s1 * 0.03125f;
    float var = fmaf(-mu, mu, s2 * 0.03125f);
    float rstd = rsqrtf(var + 1e-5f);

    float4 gm = *(const float4*)(gam + j0);
    float4 bt = *(const float4*)(bet + j0);
    gs[i * 33 + j0 + 0] = sigmoid_((v.x - mu) * rstd * gm.x + bt.x);
    gs[i * 33 + j0 + 1] = sigmoid_((v.y - mu) * rstd * gm.y + bt.y);
    gs[i * 33 + j0 + 2] = sigmoid_((v.z - mu) * rstd * gm.z + bt.z);
    gs[i * 33 + j0 + 3] = sigmoid_((v.w - mu) * rstd * gm.w + bt.w);
    if (tid < 32) ss[tid] = g_sg2[(size_t)bc * 1024 + tid * 32 + t];
    __syncthreads();

    float4 xv = ((const float4*)(x + (size_t)bct * 1024))[tid];
    int jj = tid >> 3, i0 = (tid & 7) * 4;
    float4 ov;
    ov.x = ss[i0 + 0] * gs[(i0 + 0) * 33 + jj] * xv.x;
    ov.y = ss[i0 + 1] * gs[(i0 + 1) * 33 + jj] * xv.y;
    ov.z = ss[i0 + 2] * gs[(i0 + 2) * 33 + jj] * xv.z;
    ov.w = ss[i0 + 3] * gs[(i0 + 3) * 33 + jj] * xv.w;
    ((float4*)(out + (size_t)bct * 1024))[tid] = ov;
}

// ---------------------------------------------------------------------------
extern "C" void kernel_launch(void* const* d_in, const int* in_sizes, int n_in,
                              void* d_out, int out_size)
{
    const float* x   = (const float*)d_in[0];
    const float* pos = (const float*)d_in[1];
    const float* Wqy = (const float*)d_in[2];
    const float* W0y = (const float*)d_in[3];
    const float* gy  = (const float*)d_in[4];
    const float* by  = (const float*)d_in[5];
    const float* Wqx = (const float*)d_in[6];
    const float* W0x = (const float*)d_in[7];
    const float* gx  = (const float*)d_in[8];
    const float* bx  = (const float*)d_in[9];
    float* out = (float*)d_out;

    int B = in_sizes[0] / 98304;  // 3*32*32*32

    const int SMEM_Y = (32 * WS + 32 * W0S + 4 * (2 * 32 * ST + 32 * KVS)) * 4;  // 74,752 B
    cudaFuncSetAttribute(k_attn_y7, cudaFuncAttributeMaxDynamicSharedMemorySize, SMEM_Y);

    int nY = B * 24;
    int h1 = nY / 2;
    int nb4 = B / 4;

    k_emb2<<<B * 3, 256>>>(x, pos);
    k_attn_x2<<<3 * nb4, 128>>>(Wqx, W0x, gx, bx, nb4);
    k_attn_y7<<<h1, 128, SMEM_Y>>>(Wqy, W0y, 0);
    k_attn_y7<<<nY - h1, 128, SMEM_Y>>>(Wqy, W0y, h1);
    k_final<<<B * 96, 256>>>(x, gy, by, out);
}